// round 11
// baseline (speedup 1.0000x reference)
#include <cuda_runtime.h>
#include <cuda_fp16.h>
#include <math.h>
#include <stdint.h>

#define NROWS 8192
#define DIN   512
#define HID   1024
#define EMBD  64
#define NCONS 62
#define NCLS  16
#define MAXC  1024
#define KSPLIT2 4

typedef __half h16;

// ---------------- scratch (device globals; no allocation) ----------------
__device__ h16   g_dataHi[NROWS * DIN], g_dataLo[NROWS * DIN];
__device__ h16   g_h1Hi[NROWS * HID],  g_h1Lo[NROWS * HID];
__device__ h16   g_embHi[NROWS * EMBD], g_embLo[NROWS * EMBD];
__device__ h16   g_h2Hi[NROWS * HID],  g_h2Lo[NROWS * HID];
__device__ float g_emb[NROWS * EMBD];
__device__ float g_embPart[KSPLIT2 * NROWS * EMBD];
__device__ h16   g_W1t[HID * DIN];
__device__ h16   g_W2t[EMBD * HID];
__device__ h16   g_W3t[HID * EMBD];
__device__ h16   g_W4t[DIN * HID];
__device__ int   g_labels[NROWS];
__device__ float g_clsSum[NCLS * 64];
__device__ float g_clsSq[NCLS];
__device__ int   g_clsCnt[NCLS];
__device__ int   g_members[NCLS * MAXC];
__device__ float g_hinge;

// ---------------- small helpers ----------------
__device__ __forceinline__ void split2h(float v, h16& h, h16& l) {
    h = __float2half(v);
    l = __float2half(v - __half2float(h));
}

__device__ __forceinline__ float fast_tanh(float x) {
    float e = __expf(2.0f * x);
    return 1.0f - __fdividef(2.0f, e + 1.0f);
}

__device__ __forceinline__ uint32_t s2u(const void* p) {
    uint32_t r;
    asm("{ .reg .u64 t; cvta.to.shared.u64 t, %1; cvt.u32.u64 %0, t; }" : "=r"(r) : "l"(p));
    return r;
}

#define LDSM4(r0, r1, r2, r3, addr) \
    asm volatile("ldmatrix.sync.aligned.m8n8.x4.shared.b16 {%0,%1,%2,%3}, [%4];" \
                 : "=r"(r0), "=r"(r1), "=r"(r2), "=r"(r3) : "r"(addr))

#define MMA16816(c, a, b) \
    asm volatile("mma.sync.aligned.m16n8k16.row.col.f32.f16.f16.f32 " \
                 "{%0,%1,%2,%3}, {%4,%5,%6,%7}, {%8,%9}, {%0,%1,%2,%3};" \
                 : "+f"((c)[0]), "+f"((c)[1]), "+f"((c)[2]), "+f"((c)[3]) \
                 : "r"((a)[0]), "r"((a)[1]), "r"((a)[2]), "r"((a)[3]), \
                   "r"((b)[0]), "r"((b)[1]))

#define CPASYNC16(dst, src) \
    asm volatile("cp.async.cg.shared.global [%0], [%1], 16;" :: "r"(dst), "l"(src))

// row stride in SMEM: 40 h16 = 80 bytes (odd multiple of 16B -> conflict-free ldmatrix)
#define RSTRIDE 80

// ---------------- init ----------------
__global__ void init_kernel() {
    int t = threadIdx.x;
    for (int i = t; i < NCLS * 64; i += 256) g_clsSum[i] = 0.f;
    if (t < NCLS) { g_clsSq[t] = 0.f; g_clsCnt[t] = 0; }
    if (t == 0) g_hinge = 0.f;
}

// ---------------- pack ----------------
__global__ void pack_split(const float* __restrict__ x) {
    int i = blockIdx.x * 1024 + threadIdx.x;      // exactly NROWS*DIN threads
    int r = i >> 9, c = i & 511;
    float v = x[(size_t)r * (DIN + 1) + 1 + c];
    h16 h, l; split2h(v, h, l);
    g_dataHi[i] = h; g_dataLo[i] = l;
    if (i < NROWS) g_labels[i] = (int)x[(size_t)i * (DIN + 1)];
}

// ---------------- fused weight transpose (hi only) ----------------
__global__ void wtrans_all(const float* __restrict__ W1, const float* __restrict__ W2,
                           const float* __restrict__ W3, const float* __restrict__ W4) {
    __shared__ float t[32][33];
    int b = blockIdx.x;
    const float* W; h16* T; int K, N, bx, by;
    if (b < 512)      { W = W1; T = g_W1t; K = DIN;  N = HID;  int u = b;       bx = u % 32; by = u / 32; }
    else if (b < 576) { W = W2; T = g_W2t; K = HID;  N = EMBD; int u = b - 512; bx = u % 2;  by = u / 2;  }
    else if (b < 640) { W = W3; T = g_W3t; K = EMBD; N = HID;  int u = b - 576; bx = u % 32; by = u / 32; }
    else              { W = W4; T = g_W4t; K = HID;  N = DIN;  int u = b - 640; bx = u % 16; by = u / 16; }
    int tx = threadIdx.x, ty = threadIdx.y;
    int n0 = bx * 32, k0 = by * 32;
    t[ty][tx] = W[(size_t)(k0 + ty) * N + n0 + tx];
    __syncthreads();
    T[(size_t)(n0 + ty) * K + k0 + tx] = __float2half(t[tx][ty]);
}

// ---------------- fp16-split 2-pass mma.sync GEMM (STAGES-deep cp.async) ----------------
// C[M,N] = act(A[M,K] @ W[K,N] + bias) ~= act((Ah+Al) @ Bh + bias)
template<int BM, int BN, int WM, int WN, int STAGES, bool DOTANH, bool WF32, bool WBF, bool WBIAS>
__global__ void __launch_bounds__(32 * (BM / WM) * (BN / WN), 2)
gemm_mma(const h16* __restrict__ Ahi, const h16* __restrict__ Alo,
         const h16* __restrict__ Bhi,
         const float* __restrict__ bias,
         float* __restrict__ Cf, h16* __restrict__ CHi, h16* __restrict__ CLo,
         int N, int K, int kslice, size_t cfz)
{
    constexpr int WARPS_N = BN / WN;
    constexpr int NWARP   = (BM / WM) * WARPS_N;
    constexpr int THREADS = 32 * NWARP;
    constexpr int MI = WM / 16;
    constexpr int NJ = WN / 8;
    constexpr int ASZ   = BM * RSTRIDE;
    constexpr int BSZ   = BN * RSTRIDE;
    constexpr int STAGE = 2 * ASZ + BSZ;

    extern __shared__ char smem[];
    const uint32_t sb0 = s2u(smem);
    const int tid = threadIdx.x, lane = tid & 31, wid = tid >> 5;
    const int warp_m = wid / WARPS_N, warp_n = wid % WARPS_N;
    const int bx = blockIdx.x, by = blockIdx.y;
    const int kz = blockIdx.z;
    const int korig = kz * kslice;

    const h16* aH = Ahi + (size_t)by * BM * K + korig;
    const h16* aL = Alo + (size_t)by * BM * K + korig;
    const h16* bH = Bhi + (size_t)bx * BN * K + korig;
    float* Cfp = Cf + (size_t)kz * cfz;

    const int KC = kslice >> 5;

    auto load_chunk = [&](int s, int kc) {
        uint32_t base = sb0 + s * STAGE;
        const int k0 = kc * 32;
        for (int idx = tid; idx < BM * 4; idx += THREADS) {
            int r = idx >> 2, p = idx & 3;
            uint32_t so = r * RSTRIDE + p * 16;
            CPASYNC16(base + so,        aH + (size_t)r * K + k0 + p * 8);
            CPASYNC16(base + ASZ + so,  aL + (size_t)r * K + k0 + p * 8);
        }
        for (int idx = tid; idx < BN * 4; idx += THREADS) {
            int r = idx >> 2, p = idx & 3;
            uint32_t so = r * RSTRIDE + p * 16;
            CPASYNC16(base + 2 * ASZ + so, bH + (size_t)r * K + k0 + p * 8);
        }
        asm volatile("cp.async.commit_group;");
    };

    float acc[MI][NJ][4];
#pragma unroll
    for (int i = 0; i < MI; i++)
#pragma unroll
        for (int j = 0; j < NJ; j++)
#pragma unroll
            for (int q = 0; q < 4; q++) acc[i][j][q] = 0.f;

#pragma unroll
    for (int s = 0; s < STAGES - 1; s++)
        if (s < KC) load_chunk(s, s);

    for (int kc = 0; kc < KC; kc++) {
        if (kc + STAGES - 1 < KC) {
            load_chunk((kc + STAGES - 1) % STAGES, kc + STAGES - 1);
            asm volatile("cp.async.wait_group %0;" :: "n"(STAGES - 1));
        } else {
            asm volatile("cp.async.wait_group 0;");
        }
        __syncthreads();

        uint32_t base = sb0 + (kc % STAGES) * STAGE;
        uint32_t aHb = base, aLb = base + ASZ, bHb = base + 2 * ASZ;

#pragma unroll
        for (int s16 = 0; s16 < 2; s16++) {
            uint32_t koff = s16 * 32 + ((lane >> 4) << 4);
            uint32_t ah[MI][4], al[MI][4], b[NJ][2];
#pragma unroll
            for (int mi = 0; mi < MI; mi++) {
                uint32_t ro = (uint32_t)(warp_m * WM + mi * 16 + (lane & 15)) * RSTRIDE + koff;
                LDSM4(ah[mi][0], ah[mi][1], ah[mi][2], ah[mi][3], aHb + ro);
            }
#pragma unroll
            for (int njp = 0; njp < NJ / 2; njp++) {
                uint32_t ro = (uint32_t)(warp_n * WN + njp * 16 + (lane & 15)) * RSTRIDE + koff;
                uint32_t r0, r1, r2, r3;
                LDSM4(r0, r1, r2, r3, bHb + ro);
                b[2 * njp][0] = r0; b[2 * njp + 1][0] = r1;
                b[2 * njp][1] = r2; b[2 * njp + 1][1] = r3;
            }
#pragma unroll
            for (int mi = 0; mi < MI; mi++) {
                uint32_t ro = (uint32_t)(warp_m * WM + mi * 16 + (lane & 15)) * RSTRIDE + koff;
                LDSM4(al[mi][0], al[mi][1], al[mi][2], al[mi][3], aLb + ro);
            }
            // hh pass
#pragma unroll
            for (int mi = 0; mi < MI; mi++)
#pragma unroll
                for (int nj = 0; nj < NJ; nj++)
                    MMA16816(acc[mi][nj], ah[mi], b[nj]);
            // lh pass (Al x Bh)
#pragma unroll
            for (int mi = 0; mi < MI; mi++)
#pragma unroll
                for (int nj = 0; nj < NJ; nj++)
                    MMA16816(acc[mi][nj], al[mi], b[nj]);
        }
        __syncthreads();
    }

    // ---------------- epilogue ----------------
#pragma unroll
    for (int mi = 0; mi < MI; mi++) {
#pragma unroll
        for (int nj = 0; nj < NJ; nj++) {
            int gr0 = by * BM + warp_m * WM + mi * 16 + (lane >> 2);
            int gc  = bx * BN + warp_n * WN + nj * 8 + 2 * (lane & 3);
            float bia0 = WBIAS ? bias[gc]     : 0.f;
            float bia1 = WBIAS ? bias[gc + 1] : 0.f;
#pragma unroll
            for (int half = 0; half < 2; half++) {
                int gr = gr0 + half * 8;
                float v0 = acc[mi][nj][2 * half]     + bia0;
                float v1 = acc[mi][nj][2 * half + 1] + bia1;
                if (DOTANH) { v0 = fast_tanh(v0); v1 = fast_tanh(v1); }
                if (WF32) {
                    *(float2*)&Cfp[(size_t)gr * N + gc] = make_float2(v0, v1);
                }
                if (WBF) {
                    h16 h0, l0, h1, l1;
                    split2h(v0, h0, l0); split2h(v1, h1, l1);
                    *(__half2*)&CHi[(size_t)gr * N + gc] = __halves2half2(h0, h1);
                    *(__half2*)&CLo[(size_t)gr * N + gc] = __halves2half2(l0, l1);
                }
            }
        }
    }
}

// ---------------- GEMM2 split-K reduce: partials + bias -> g_emb, hi/lo ----------------
__global__ void emb_epi(const float* __restrict__ b2) {
    int i = blockIdx.x * 256 + threadIdx.x;       // NROWS*EMBD threads
    int c = i & (EMBD - 1);
    const int S = NROWS * EMBD;
    float v = g_embPart[i] + g_embPart[i + S] + g_embPart[i + 2 * S] + g_embPart[i + 3 * S]
            + b2[c];
    g_emb[i] = v;
    h16 h, l; split2h(v, h, l);
    g_embHi[i] = h; g_embLo[i] = l;
}

// ---------------- per-class sums, counts, member lists ----------------
__global__ void class_accum_kernel() {
    __shared__ float sSum[NCLS][64];
    __shared__ float sSq[NCLS];
    int tid = threadIdx.x;
    for (int i = tid; i < NCLS * 64; i += 256) ((float*)sSum)[i] = 0.f;
    if (tid < NCLS) sSq[tid] = 0.f;
    __syncthreads();

    int r = blockIdx.x * 256 + tid;
    int c = g_labels[r];
    const float* e = g_emb + (size_t)r * EMBD + 2;
    float sq = 0.f;
#pragma unroll
    for (int k = 0; k < NCONS; k++) {
        float v = e[k];
        sq = fmaf(v, v, sq);
        atomicAdd(&sSum[c][k], v);
    }
    atomicAdd(&sSq[c], sq);
    int pos = atomicAdd(&g_clsCnt[c], 1);
    if (pos < MAXC) g_members[c * MAXC + pos] = r;
    __syncthreads();

    for (int i = tid; i < NCLS * 64; i += 256) atomicAdd(&g_clsSum[i], ((float*)sSum)[i]);
    if (tid < NCLS) atomicAdd(&g_clsSq[tid], sSq[tid]);
}

// ---------------- same-class pairwise hinge (triangle x2, 64x64 tile, 4x4/thread) ----------------
__global__ void pair_kernel() {
    int c = blockIdx.z;
    int i0 = blockIdx.y * 64, j0 = blockIdx.x * 64;
    if (j0 > i0) return;
    int cnt = g_clsCnt[c]; if (cnt > MAXC) cnt = MAXC;
    if (i0 >= cnt || j0 >= cnt) return;
    float scale = (j0 < i0) ? 2.f : 1.f;

    __shared__ float va[64][63];
    __shared__ float vb[64][63];
    int tx = threadIdx.x, ty = threadIdx.y;    // 16 x 16
    int tid = ty * 16 + tx;

    // load 64 rows of each side: 4 threads per row, k strided by 4
    {
        int r = tid >> 2, kk = tid & 3;
        int mi = g_members[c * MAXC + i0 + r];
        int mj = g_members[c * MAXC + j0 + r];
        bool iv = (i0 + r < cnt), jv = (j0 + r < cnt);
        const float* ei = g_emb + (size_t)mi * EMBD + 2;
        const float* ej = g_emb + (size_t)mj * EMBD + 2;
        for (int k = kk; k < NCONS; k += 4) {
            if (iv) va[r][k] = ei[k];
            if (jv) vb[r][k] = ej[k];
        }
    }
    __syncthreads();

    // 4x4 outputs: rows ty+16q vs cols tx+16p
    float d[4][4];
#pragma unroll
    for (int q = 0; q < 4; q++)
#pragma unroll
        for (int p = 0; p < 4; p++) d[q][p] = 0.f;
#pragma unroll
    for (int k = 0; k < NCONS; k++) {
        float a[4], bb[4];
#pragma unroll
        for (int q = 0; q < 4; q++) a[q] = va[ty + 16 * q][k];
#pragma unroll
        for (int p = 0; p < 4; p++) bb[p] = vb[tx + 16 * p][k];
#pragma unroll
        for (int q = 0; q < 4; q++)
#pragma unroll
            for (int p = 0; p < 4; p++) {
                float x = a[q] - bb[p];
                d[q][p] = fmaf(x, x, d[q][p]);
            }
    }
    const float inv = 1.0f / (float)NCONS;
    float h = 0.f;
#pragma unroll
    for (int q = 0; q < 4; q++) {
        bool iv = (i0 + ty + 16 * q < cnt);
#pragma unroll
        for (int p = 0; p < 4; p++) {
            bool jv = (j0 + tx + 16 * p < cnt);
            if (iv && jv) h += fmaxf(0.f, 0.01f - d[q][p] * inv);
        }
    }

#pragma unroll
    for (int o = 16; o > 0; o >>= 1) h += __shfl_down_sync(0xffffffffu, h, o);
    __shared__ float ws[8];
    int lane = tid & 31, wrp = tid >> 5;
    if (lane == 0) ws[wrp] = h;
    __syncthreads();
    if (tid < 8) {
        float v = ws[tid];
#pragma unroll
        for (int o = 4; o > 0; o >>= 1) v += __shfl_down_sync(0xffu, v, o);
        if (tid == 0) atomicAdd(&g_hinge, v * scale);
    }
}

// ---------------- finalize scalars (64 threads, fp64) ----------------
__global__ void finalize_kernel(float* __restrict__ out) {
    __shared__ double red[64];
    int k = threadIdx.x;
    double stk = 0.0;
    double same = 0.0, Stot = 0.0, n_same = 0.0;
    for (int c = 0; c < NCLS; c++) {
        double v = (k < NCONS) ? (double)g_clsSum[c * 64 + k] : 0.0;
        stk += v;
        red[k] = v * v;
        __syncthreads();
        for (int o = 32; o > 0; o >>= 1) {
            if (k < o) red[k] += red[k + o];
            __syncthreads();
        }
        if (k == 0) {
            double nc = (double)g_clsCnt[c], Sc = (double)g_clsSq[c];
            same  += 2.0 * nc * Sc - 2.0 * red[0];
            Stot  += Sc;
            n_same += nc * nc;
        }
        __syncthreads();
    }
    red[k] = stk * stk;
    __syncthreads();
    for (int o = 32; o > 0; o >>= 1) {
        if (k < o) red[k] += red[k + o];
        __syncthreads();
    }
    if (k == 0) {
        double stot2 = red[0];
        double total = (2.0 * (double)NROWS * Stot - 2.0 * stot2) / (double)NCONS;
        same /= (double)NCONS;
        double n_diff = (double)NROWS * (double)NROWS - n_same;
        out[(size_t)NROWS * DIN]     = (float)((total - same) / (n_diff + 1.0));
        out[(size_t)NROWS * DIN + 1] = (float)((double)g_hinge / (n_same + 1.0));
    }
}

// ---------------- launch ----------------
extern "C" void kernel_launch(void* const* d_in, const int* in_sizes, int n_in,
                              void* d_out, int out_size)
{
    (void)in_sizes; (void)n_in; (void)out_size;
    const float* x  = (const float*)d_in[0];
    const float* W1 = (const float*)d_in[1];
    const float* b1 = (const float*)d_in[2];
    const float* W2 = (const float*)d_in[3];
    const float* b2 = (const float*)d_in[4];
    const float* W3 = (const float*)d_in[5];
    const float* b3 = (const float*)d_in[6];
    const float* W4 = (const float*)d_in[7];
    const float* b4 = (const float*)d_in[8];
    float* out = (float*)d_out;

    void *pdH, *pdL, *p1H, *p1L, *peH, *peL, *p2H, *p2L, *pe, *pep;
    void *w1, *w2, *w3, *w4;
    cudaGetSymbolAddress(&pdH, g_dataHi); cudaGetSymbolAddress(&pdL, g_dataLo);
    cudaGetSymbolAddress(&p1H, g_h1Hi);   cudaGetSymbolAddress(&p1L, g_h1Lo);
    cudaGetSymbolAddress(&peH, g_embHi);  cudaGetSymbolAddress(&peL, g_embLo);
    cudaGetSymbolAddress(&p2H, g_h2Hi);   cudaGetSymbolAddress(&p2L, g_h2Lo);
    cudaGetSymbolAddress(&pe,  g_emb);    cudaGetSymbolAddress(&pep, g_embPart);
    cudaGetSymbolAddress(&w1,  g_W1t);    cudaGetSymbolAddress(&w2,  g_W2t);
    cudaGetSymbolAddress(&w3,  g_W3t);    cudaGetSymbolAddress(&w4,  g_W4t);

    // dynamic smem: STAGES stages; stage = (2*BM + BN)*RSTRIDE
    const int SMEM_BIG3  = 3 * (2 * 128 + 128) * RSTRIDE;   // 92160
    const int SMEM_SMALL = 2 * (2 * 64 + 64) * RSTRIDE;     // 30720
    cudaFuncSetAttribute(gemm_mma<128, 128, 64, 32, 3, true,  false, true,  true >, cudaFuncAttributeMaxDynamicSharedMemorySize, SMEM_BIG3);
    cudaFuncSetAttribute(gemm_mma<64,  64,  32, 32, 2, false, true,  false, false>, cudaFuncAttributeMaxDynamicSharedMemorySize, SMEM_SMALL);
    cudaFuncSetAttribute(gemm_mma<128, 128, 64, 32, 3, false, true,  false, true >, cudaFuncAttributeMaxDynamicSharedMemorySize, SMEM_BIG3);

    init_kernel<<<1, 256>>>();                               // launch 1
    pack_split<<<NROWS * DIN / 1024, 1024>>>(x);             // launch 2
    wtrans_all<<<1152, dim3(32, 32)>>>(W1, W2, W3, W4);      // launch 3

    // h1 = tanh(data @ W1 + b1)   M=8192, N=1024, K=512     // launch 4 (ncu slot)
    gemm_mma<128, 128, 64, 32, 3, true, false, true, true><<<dim3(HID / 128, NROWS / 128), 256, SMEM_BIG3>>>(
        (h16*)pdH, (h16*)pdL, (h16*)w1, b1,
        nullptr, (h16*)p1H, (h16*)p1L, HID, DIN, DIN, 0);
    // emb partials: split-K=4, M=8192, N=64, K=1024 -> fp32 partials
    gemm_mma<64, 64, 32, 32, 2, false, true, false, false><<<dim3(1, NROWS / 64, KSPLIT2), 128, SMEM_SMALL>>>(
        (h16*)p1H, (h16*)p1L, (h16*)w2, b2,
        (float*)pep, nullptr, nullptr, EMBD, HID, HID / KSPLIT2, (size_t)NROWS * EMBD);
    // reduce partials + bias -> g_emb, hi/lo
    emb_epi<<<NROWS * EMBD / 256, 256>>>(b2);
    // h2 = tanh(emb @ W3 + b3)    M=8192, N=1024, K=64
    gemm_mma<128, 128, 64, 32, 3, true, false, true, true><<<dim3(HID / 128, NROWS / 128), 256, SMEM_BIG3>>>(
        (h16*)peH, (h16*)peL, (h16*)w3, b3,
        nullptr, (h16*)p2H, (h16*)p2L, HID, EMBD, EMBD, 0);
    // decoded = h2 @ W4 + b4      M=8192, N=512, K=1024 -> fp32 out
    gemm_mma<128, 128, 64, 32, 3, false, true, false, true><<<dim3(DIN / 128, NROWS / 128), 256, SMEM_BIG3>>>(
        (h16*)p2H, (h16*)p2L, (h16*)w4, b4,
        out, nullptr, nullptr, DIN, HID, HID, 0);

    class_accum_kernel<<<NROWS / 256, 256>>>();
    pair_kernel<<<dim3(MAXC / 64, MAXC / 64, NCLS), dim3(16, 16)>>>();
    finalize_kernel<<<1, 64>>>(out);
}

// round 12
// speedup vs baseline: 1.0325x; 1.0325x over previous
#include <cuda_runtime.h>
#include <cuda_fp16.h>
#include <math.h>
#include <stdint.h>

#define NROWS 8192
#define DIN   512
#define HID   1024
#define EMBD  64
#define NCONS 62
#define NCLS  16
#define MAXC  1024
#define KSPLIT2 4

typedef __half h16;

// ---------------- scratch (device globals; no allocation) ----------------
__device__ h16   g_dataHi[NROWS * DIN], g_dataLo[NROWS * DIN];
__device__ h16   g_h1Hi[NROWS * HID],  g_h1Lo[NROWS * HID];
__device__ h16   g_embHi[NROWS * EMBD], g_embLo[NROWS * EMBD];
__device__ h16   g_h2Hi[NROWS * HID],  g_h2Lo[NROWS * HID];
__device__ float g_emb[NROWS * EMBD];
__device__ float g_embPart[KSPLIT2 * NROWS * EMBD];
__device__ h16   g_W1t[HID * DIN];
__device__ h16   g_W2t[EMBD * HID];
__device__ h16   g_W3t[HID * EMBD];
__device__ h16   g_W4t[DIN * HID];
__device__ int   g_labels[NROWS];
__device__ float g_clsSum[NCLS * 64];
__device__ float g_clsSq[NCLS];
__device__ int   g_clsCnt[NCLS];
__device__ int   g_members[NCLS * MAXC];
__device__ float g_hinge;

// ---------------- small helpers ----------------
__device__ __forceinline__ void split2h(float v, h16& h, h16& l) {
    h = __float2half(v);
    l = __float2half(v - __half2float(h));
}

__device__ __forceinline__ float fast_tanh(float x) {
    float e = __expf(2.0f * x);
    return 1.0f - __fdividef(2.0f, e + 1.0f);
}

__device__ __forceinline__ uint32_t s2u(const void* p) {
    uint32_t r;
    asm("{ .reg .u64 t; cvta.to.shared.u64 t, %1; cvt.u32.u64 %0, t; }" : "=r"(r) : "l"(p));
    return r;
}

#define LDSM4(r0, r1, r2, r3, addr) \
    asm volatile("ldmatrix.sync.aligned.m8n8.x4.shared.b16 {%0,%1,%2,%3}, [%4];" \
                 : "=r"(r0), "=r"(r1), "=r"(r2), "=r"(r3) : "r"(addr))

#define MMA16816(c, a, b) \
    asm volatile("mma.sync.aligned.m16n8k16.row.col.f32.f16.f16.f32 " \
                 "{%0,%1,%2,%3}, {%4,%5,%6,%7}, {%8,%9}, {%0,%1,%2,%3};" \
                 : "+f"((c)[0]), "+f"((c)[1]), "+f"((c)[2]), "+f"((c)[3]) \
                 : "r"((a)[0]), "r"((a)[1]), "r"((a)[2]), "r"((a)[3]), \
                   "r"((b)[0]), "r"((b)[1]))

#define CPASYNC16(dst, src) \
    asm volatile("cp.async.cg.shared.global [%0], [%1], 16;" :: "r"(dst), "l"(src))

// row stride in SMEM: 40 h16 = 80 bytes (odd multiple of 16B -> conflict-free ldmatrix)
#define RSTRIDE 80

// ---------------- pack (+ fused init) ----------------
__global__ void pack_split(const float* __restrict__ x) {
    int i = blockIdx.x * 1024 + threadIdx.x;      // exactly NROWS*DIN threads
    int r = i >> 9, c = i & 511;
    float v = x[(size_t)r * (DIN + 1) + 1 + c];
    h16 h, l; split2h(v, h, l);
    g_dataHi[i] = h; g_dataLo[i] = l;
    if (i < NROWS) g_labels[i] = (int)x[(size_t)i * (DIN + 1)];
    if (i < NCLS * 64) g_clsSum[i] = 0.f;
    if (i < NCLS) { g_clsSq[i] = 0.f; g_clsCnt[i] = 0; }
    if (i == 0) g_hinge = 0.f;
}

// ---------------- fused weight transpose (hi only) ----------------
__global__ void wtrans_all(const float* __restrict__ W1, const float* __restrict__ W2,
                           const float* __restrict__ W3, const float* __restrict__ W4) {
    __shared__ float t[32][33];
    int b = blockIdx.x;
    const float* W; h16* T; int K, N, bx, by;
    if (b < 512)      { W = W1; T = g_W1t; K = DIN;  N = HID;  int u = b;       bx = u % 32; by = u / 32; }
    else if (b < 576) { W = W2; T = g_W2t; K = HID;  N = EMBD; int u = b - 512; bx = u % 2;  by = u / 2;  }
    else if (b < 640) { W = W3; T = g_W3t; K = EMBD; N = HID;  int u = b - 576; bx = u % 32; by = u / 32; }
    else              { W = W4; T = g_W4t; K = HID;  N = DIN;  int u = b - 640; bx = u % 16; by = u / 16; }
    int tx = threadIdx.x, ty = threadIdx.y;
    int n0 = bx * 32, k0 = by * 32;
    t[ty][tx] = W[(size_t)(k0 + ty) * N + n0 + tx];
    __syncthreads();
    T[(size_t)(n0 + ty) * K + k0 + tx] = __float2half(t[tx][ty]);
}

// ---------------- fp16-split 2-pass mma.sync GEMM (2-stage cp.async, R10-proven) ----------------
// C[M,N] = act(A[M,K] @ W[K,N] + bias) ~= act((Ah+Al) @ Bh + bias)
template<int BM, int BN, int WM, int WN, bool DOTANH, bool WF32, bool WBF, bool WBIAS>
__global__ void __launch_bounds__(32 * (BM / WM) * (BN / WN), 2)
gemm_mma(const h16* __restrict__ Ahi, const h16* __restrict__ Alo,
         const h16* __restrict__ Bhi,
         const float* __restrict__ bias,
         float* __restrict__ Cf, h16* __restrict__ CHi, h16* __restrict__ CLo,
         int N, int K, int kslice, size_t cfz)
{
    constexpr int WARPS_N = BN / WN;
    constexpr int NWARP   = (BM / WM) * WARPS_N;
    constexpr int THREADS = 32 * NWARP;
    constexpr int MI = WM / 16;
    constexpr int NJ = WN / 8;
    constexpr int ASZ   = BM * RSTRIDE;
    constexpr int BSZ   = BN * RSTRIDE;
    constexpr int STAGE = 2 * ASZ + BSZ;

    extern __shared__ char smem[];
    const uint32_t sb0 = s2u(smem);
    const int tid = threadIdx.x, lane = tid & 31, wid = tid >> 5;
    const int warp_m = wid / WARPS_N, warp_n = wid % WARPS_N;
    const int bx = blockIdx.x, by = blockIdx.y;
    const int kz = blockIdx.z;
    const int korig = kz * kslice;

    const h16* aH = Ahi + (size_t)by * BM * K + korig;
    const h16* aL = Alo + (size_t)by * BM * K + korig;
    const h16* bH = Bhi + (size_t)bx * BN * K + korig;
    float* Cfp = Cf + (size_t)kz * cfz;

    const int KC = kslice >> 5;

    auto load_chunk = [&](int s, int kc) {
        uint32_t base = sb0 + s * STAGE;
        const int k0 = kc * 32;
        for (int idx = tid; idx < BM * 4; idx += THREADS) {
            int r = idx >> 2, p = idx & 3;
            uint32_t so = r * RSTRIDE + p * 16;
            CPASYNC16(base + so,        aH + (size_t)r * K + k0 + p * 8);
            CPASYNC16(base + ASZ + so,  aL + (size_t)r * K + k0 + p * 8);
        }
        for (int idx = tid; idx < BN * 4; idx += THREADS) {
            int r = idx >> 2, p = idx & 3;
            uint32_t so = r * RSTRIDE + p * 16;
            CPASYNC16(base + 2 * ASZ + so, bH + (size_t)r * K + k0 + p * 8);
        }
        asm volatile("cp.async.commit_group;");
    };

    float acc[MI][NJ][4];
#pragma unroll
    for (int i = 0; i < MI; i++)
#pragma unroll
        for (int j = 0; j < NJ; j++)
#pragma unroll
            for (int q = 0; q < 4; q++) acc[i][j][q] = 0.f;

    load_chunk(0, 0);

    for (int kc = 0; kc < KC; kc++) {
        if (kc + 1 < KC) {
            load_chunk((kc + 1) & 1, kc + 1);
            asm volatile("cp.async.wait_group 1;");
        } else {
            asm volatile("cp.async.wait_group 0;");
        }
        __syncthreads();

        uint32_t base = sb0 + (kc & 1) * STAGE;
        uint32_t aHb = base, aLb = base + ASZ, bHb = base + 2 * ASZ;

#pragma unroll
        for (int s16 = 0; s16 < 2; s16++) {
            uint32_t koff = s16 * 32 + ((lane >> 4) << 4);
            uint32_t ah[MI][4], al[MI][4], b[NJ][2];
#pragma unroll
            for (int mi = 0; mi < MI; mi++) {
                uint32_t ro = (uint32_t)(warp_m * WM + mi * 16 + (lane & 15)) * RSTRIDE + koff;
                LDSM4(ah[mi][0], ah[mi][1], ah[mi][2], ah[mi][3], aHb + ro);
            }
#pragma unroll
            for (int njp = 0; njp < NJ / 2; njp++) {
                uint32_t ro = (uint32_t)(warp_n * WN + njp * 16 + (lane & 15)) * RSTRIDE + koff;
                uint32_t r0, r1, r2, r3;
                LDSM4(r0, r1, r2, r3, bHb + ro);
                b[2 * njp][0] = r0; b[2 * njp + 1][0] = r1;
                b[2 * njp][1] = r2; b[2 * njp + 1][1] = r3;
            }
#pragma unroll
            for (int mi = 0; mi < MI; mi++) {
                uint32_t ro = (uint32_t)(warp_m * WM + mi * 16 + (lane & 15)) * RSTRIDE + koff;
                LDSM4(al[mi][0], al[mi][1], al[mi][2], al[mi][3], aLb + ro);
            }
            // hh pass
#pragma unroll
            for (int mi = 0; mi < MI; mi++)
#pragma unroll
                for (int nj = 0; nj < NJ; nj++)
                    MMA16816(acc[mi][nj], ah[mi], b[nj]);
            // lh pass (Al x Bh)
#pragma unroll
            for (int mi = 0; mi < MI; mi++)
#pragma unroll
                for (int nj = 0; nj < NJ; nj++)
                    MMA16816(acc[mi][nj], al[mi], b[nj]);
        }
        __syncthreads();
    }

    // ---------------- epilogue ----------------
#pragma unroll
    for (int mi = 0; mi < MI; mi++) {
#pragma unroll
        for (int nj = 0; nj < NJ; nj++) {
            int gr0 = by * BM + warp_m * WM + mi * 16 + (lane >> 2);
            int gc  = bx * BN + warp_n * WN + nj * 8 + 2 * (lane & 3);
            float bia0 = WBIAS ? bias[gc]     : 0.f;
            float bia1 = WBIAS ? bias[gc + 1] : 0.f;
#pragma unroll
            for (int half = 0; half < 2; half++) {
                int gr = gr0 + half * 8;
                float v0 = acc[mi][nj][2 * half]     + bia0;
                float v1 = acc[mi][nj][2 * half + 1] + bia1;
                if (DOTANH) { v0 = fast_tanh(v0); v1 = fast_tanh(v1); }
                if (WF32) {
                    *(float2*)&Cfp[(size_t)gr * N + gc] = make_float2(v0, v1);
                }
                if (WBF) {
                    h16 h0, l0, h1, l1;
                    split2h(v0, h0, l0); split2h(v1, h1, l1);
                    *(__half2*)&CHi[(size_t)gr * N + gc] = __halves2half2(h0, h1);
                    *(__half2*)&CLo[(size_t)gr * N + gc] = __halves2half2(l0, l1);
                }
            }
        }
    }
}

// ---------------- GEMM2 split-K reduce: partials + bias -> g_emb, hi/lo ----------------
__global__ void emb_epi(const float* __restrict__ b2) {
    int i = blockIdx.x * 256 + threadIdx.x;       // NROWS*EMBD threads
    int c = i & (EMBD - 1);
    const int S = NROWS * EMBD;
    float v = g_embPart[i] + g_embPart[i + S] + g_embPart[i + 2 * S] + g_embPart[i + 3 * S]
            + b2[c];
    g_emb[i] = v;
    h16 h, l; split2h(v, h, l);
    g_embHi[i] = h; g_embLo[i] = l;
}

// ---------------- per-class sums, counts, member lists ----------------
__global__ void class_accum_kernel() {
    __shared__ float sSum[NCLS][64];
    __shared__ float sSq[NCLS];
    int tid = threadIdx.x;
    for (int i = tid; i < NCLS * 64; i += 256) ((float*)sSum)[i] = 0.f;
    if (tid < NCLS) sSq[tid] = 0.f;
    __syncthreads();

    int r = blockIdx.x * 256 + tid;
    int c = g_labels[r];
    const float* e = g_emb + (size_t)r * EMBD + 2;
    float sq = 0.f;
#pragma unroll
    for (int k = 0; k < NCONS; k++) {
        float v = e[k];
        sq = fmaf(v, v, sq);
        atomicAdd(&sSum[c][k], v);
    }
    atomicAdd(&sSq[c], sq);
    int pos = atomicAdd(&g_clsCnt[c], 1);
    if (pos < MAXC) g_members[c * MAXC + pos] = r;
    __syncthreads();

    for (int i = tid; i < NCLS * 64; i += 256) atomicAdd(&g_clsSum[i], ((float*)sSum)[i]);
    if (tid < NCLS) atomicAdd(&g_clsSq[tid], sSq[tid]);
}

// ---------------- same-class pairwise hinge (triangle x2, 64x64 tile, 4x4/thread) ----------------
__global__ void pair_kernel() {
    int c = blockIdx.z;
    int i0 = blockIdx.y * 64, j0 = blockIdx.x * 64;
    if (j0 > i0) return;
    int cnt = g_clsCnt[c]; if (cnt > MAXC) cnt = MAXC;
    if (i0 >= cnt || j0 >= cnt) return;
    float scale = (j0 < i0) ? 2.f : 1.f;

    __shared__ float va[64][63];
    __shared__ float vb[64][63];
    int tx = threadIdx.x, ty = threadIdx.y;    // 16 x 16
    int tid = ty * 16 + tx;

    {
        int r = tid >> 2, kk = tid & 3;
        int mi = g_members[c * MAXC + i0 + r];
        int mj = g_members[c * MAXC + j0 + r];
        bool iv = (i0 + r < cnt), jv = (j0 + r < cnt);
        const float* ei = g_emb + (size_t)mi * EMBD + 2;
        const float* ej = g_emb + (size_t)mj * EMBD + 2;
        for (int k = kk; k < NCONS; k += 4) {
            if (iv) va[r][k] = ei[k];
            if (jv) vb[r][k] = ej[k];
        }
    }
    __syncthreads();

    float d[4][4];
#pragma unroll
    for (int q = 0; q < 4; q++)
#pragma unroll
        for (int p = 0; p < 4; p++) d[q][p] = 0.f;
#pragma unroll
    for (int k = 0; k < NCONS; k++) {
        float a[4], bb[4];
#pragma unroll
        for (int q = 0; q < 4; q++) a[q] = va[ty + 16 * q][k];
#pragma unroll
        for (int p = 0; p < 4; p++) bb[p] = vb[tx + 16 * p][k];
#pragma unroll
        for (int q = 0; q < 4; q++)
#pragma unroll
            for (int p = 0; p < 4; p++) {
                float x = a[q] - bb[p];
                d[q][p] = fmaf(x, x, d[q][p]);
            }
    }
    const float inv = 1.0f / (float)NCONS;
    float h = 0.f;
#pragma unroll
    for (int q = 0; q < 4; q++) {
        bool iv = (i0 + ty + 16 * q < cnt);
#pragma unroll
        for (int p = 0; p < 4; p++) {
            bool jv = (j0 + tx + 16 * p < cnt);
            if (iv && jv) h += fmaxf(0.f, 0.01f - d[q][p] * inv);
        }
    }

#pragma unroll
    for (int o = 16; o > 0; o >>= 1) h += __shfl_down_sync(0xffffffffu, h, o);
    __shared__ float ws[8];
    int lane = tid & 31, wrp = tid >> 5;
    if (lane == 0) ws[wrp] = h;
    __syncthreads();
    if (tid < 8) {
        float v = ws[tid];
#pragma unroll
        for (int o = 4; o > 0; o >>= 1) v += __shfl_down_sync(0xffu, v, o);
        if (tid == 0) atomicAdd(&g_hinge, v * scale);
    }
}

// ---------------- finalize scalars (64 threads, fp64) ----------------
__global__ void finalize_kernel(float* __restrict__ out) {
    __shared__ double red[64];
    int k = threadIdx.x;
    double stk = 0.0;
    double same = 0.0, Stot = 0.0, n_same = 0.0;
    for (int c = 0; c < NCLS; c++) {
        double v = (k < NCONS) ? (double)g_clsSum[c * 64 + k] : 0.0;
        stk += v;
        red[k] = v * v;
        __syncthreads();
        for (int o = 32; o > 0; o >>= 1) {
            if (k < o) red[k] += red[k + o];
            __syncthreads();
        }
        if (k == 0) {
            double nc = (double)g_clsCnt[c], Sc = (double)g_clsSq[c];
            same  += 2.0 * nc * Sc - 2.0 * red[0];
            Stot  += Sc;
            n_same += nc * nc;
        }
        __syncthreads();
    }
    red[k] = stk * stk;
    __syncthreads();
    for (int o = 32; o > 0; o >>= 1) {
        if (k < o) red[k] += red[k + o];
        __syncthreads();
    }
    if (k == 0) {
        double stot2 = red[0];
        double total = (2.0 * (double)NROWS * Stot - 2.0 * stot2) / (double)NCONS;
        same /= (double)NCONS;
        double n_diff = (double)NROWS * (double)NROWS - n_same;
        out[(size_t)NROWS * DIN]     = (float)((total - same) / (n_diff + 1.0));
        out[(size_t)NROWS * DIN + 1] = (float)((double)g_hinge / (n_same + 1.0));
    }
}

// ---------------- launch ----------------
extern "C" void kernel_launch(void* const* d_in, const int* in_sizes, int n_in,
                              void* d_out, int out_size)
{
    (void)in_sizes; (void)n_in; (void)out_size;
    const float* x  = (const float*)d_in[0];
    const float* W1 = (const float*)d_in[1];
    const float* b1 = (const float*)d_in[2];
    const float* W2 = (const float*)d_in[3];
    const float* b2 = (const float*)d_in[4];
    const float* W3 = (const float*)d_in[5];
    const float* b3 = (const float*)d_in[6];
    const float* W4 = (const float*)d_in[7];
    const float* b4 = (const float*)d_in[8];
    float* out = (float*)d_out;

    void *pdH, *pdL, *p1H, *p1L, *peH, *peL, *p2H, *p2L, *pe, *pep;
    void *w1, *w2, *w3, *w4;
    cudaGetSymbolAddress(&pdH, g_dataHi); cudaGetSymbolAddress(&pdL, g_dataLo);
    cudaGetSymbolAddress(&p1H, g_h1Hi);   cudaGetSymbolAddress(&p1L, g_h1Lo);
    cudaGetSymbolAddress(&peH, g_embHi);  cudaGetSymbolAddress(&peL, g_embLo);
    cudaGetSymbolAddress(&p2H, g_h2Hi);   cudaGetSymbolAddress(&p2L, g_h2Lo);
    cudaGetSymbolAddress(&pe,  g_emb);    cudaGetSymbolAddress(&pep, g_embPart);
    cudaGetSymbolAddress(&w1,  g_W1t);    cudaGetSymbolAddress(&w2,  g_W2t);
    cudaGetSymbolAddress(&w3,  g_W3t);    cudaGetSymbolAddress(&w4,  g_W4t);

    // dynamic smem: 2 stages; stage = (2*BM + BN)*RSTRIDE
    const int SMEM_BIG   = 2 * (2 * 128 + 128) * RSTRIDE;   // 61440
    const int SMEM_SMALL = 2 * (2 * 64 + 64) * RSTRIDE;     // 30720
    cudaFuncSetAttribute(gemm_mma<128, 128, 64, 32, true,  false, true,  true >, cudaFuncAttributeMaxDynamicSharedMemorySize, SMEM_BIG);
    cudaFuncSetAttribute(gemm_mma<64,  64,  32, 32, false, true,  false, false>, cudaFuncAttributeMaxDynamicSharedMemorySize, SMEM_SMALL);
    cudaFuncSetAttribute(gemm_mma<128, 128, 64, 32, false, true,  false, true >, cudaFuncAttributeMaxDynamicSharedMemorySize, SMEM_BIG);

    pack_split<<<NROWS * DIN / 1024, 1024>>>(x);             // launch 1 (init fused)
    wtrans_all<<<1152, dim3(32, 32)>>>(W1, W2, W3, W4);      // launch 2

    // h1 = tanh(data @ W1 + b1)   M=8192, N=1024, K=512
    gemm_mma<128, 128, 64, 32, true, false, true, true><<<dim3(HID / 128, NROWS / 128), 256, SMEM_BIG>>>(
        (h16*)pdH, (h16*)pdL, (h16*)w1, b1,
        nullptr, (h16*)p1H, (h16*)p1L, HID, DIN, DIN, 0);
    // emb partials: split-K=4, M=8192, N=64, K=1024 -> fp32 partials
    gemm_mma<64, 64, 32, 32, false, true, false, false><<<dim3(1, NROWS / 64, KSPLIT2), 128, SMEM_SMALL>>>(
        (h16*)p1H, (h16*)p1L, (h16*)w2, b2,
        (float*)pep, nullptr, nullptr, EMBD, HID, HID / KSPLIT2, (size_t)NROWS * EMBD);
    // reduce partials + bias -> g_emb, hi/lo
    emb_epi<<<NROWS * EMBD / 256, 256>>>(b2);
    // h2 = tanh(emb @ W3 + b3)    M=8192, N=1024, K=64
    gemm_mma<128, 128, 64, 32, true, false, true, true><<<dim3(HID / 128, NROWS / 128), 256, SMEM_BIG>>>(
        (h16*)peH, (h16*)peL, (h16*)w3, b3,
        nullptr, (h16*)p2H, (h16*)p2L, HID, EMBD, EMBD, 0);
    // decoded = h2 @ W4 + b4      M=8192, N=512, K=1024 -> fp32 out
    gemm_mma<128, 128, 64, 32, false, true, false, true><<<dim3(DIN / 128, NROWS / 128), 256, SMEM_BIG>>>(
        (h16*)p2H, (h16*)p2L, (h16*)w4, b4,
        out, nullptr, nullptr, DIN, HID, HID, 0);

    class_accum_kernel<<<NROWS / 256, 256>>>();
    pair_kernel<<<dim3(MAXC / 64, MAXC / 64, NCLS), dim3(16, 16)>>>();
    finalize_kernel<<<1, 64>>>(out);
}

// round 13
// speedup vs baseline: 1.0699x; 1.0362x over previous
#include <cuda_runtime.h>
#include <cuda_fp16.h>
#include <math.h>
#include <stdint.h>

#define NROWS 8192
#define DIN   512
#define HID   1024
#define EMBD  64
#define NCONS 62
#define NCLS  16
#define MAXC  1024

typedef __half h16;

// ---------------- scratch (device globals; no allocation) ----------------
__device__ h16   g_dataHi[NROWS * DIN], g_dataLo[NROWS * DIN];
__device__ h16   g_embHi[NROWS * EMBD], g_embLo[NROWS * EMBD];
__device__ h16   g_h2Hi[NROWS * HID],  g_h2Lo[NROWS * HID];
__device__ float g_emb[NROWS * EMBD];
__device__ h16   g_W1t[HID * DIN];
__device__ h16   g_W2t[EMBD * HID];
__device__ h16   g_W3t[HID * EMBD];
__device__ h16   g_W4t[DIN * HID];
__device__ int   g_labels[NROWS];
__device__ float g_clsSum[NCLS * 64];
__device__ float g_clsSq[NCLS];
__device__ int   g_clsCnt[NCLS];
__device__ int   g_members[NCLS * MAXC];
__device__ float g_hinge;

// ---------------- small helpers ----------------
__device__ __forceinline__ void split2h(float v, h16& h, h16& l) {
    h = __float2half(v);
    l = __float2half(v - __half2float(h));
}

__device__ __forceinline__ float fast_tanh(float x) {
    float e = __expf(2.0f * x);
    return 1.0f - __fdividef(2.0f, e + 1.0f);
}

__device__ __forceinline__ uint32_t s2u(const void* p) {
    uint32_t r;
    asm("{ .reg .u64 t; cvta.to.shared.u64 t, %1; cvt.u32.u64 %0, t; }" : "=r"(r) : "l"(p));
    return r;
}

#define LDSM4(r0, r1, r2, r3, addr) \
    asm volatile("ldmatrix.sync.aligned.m8n8.x4.shared.b16 {%0,%1,%2,%3}, [%4];" \
                 : "=r"(r0), "=r"(r1), "=r"(r2), "=r"(r3) : "r"(addr))

#define MMA16816(c, a, b) \
    asm volatile("mma.sync.aligned.m16n8k16.row.col.f32.f16.f16.f32 " \
                 "{%0,%1,%2,%3}, {%4,%5,%6,%7}, {%8,%9}, {%0,%1,%2,%3};" \
                 : "+f"((c)[0]), "+f"((c)[1]), "+f"((c)[2]), "+f"((c)[3]) \
                 : "r"((a)[0]), "r"((a)[1]), "r"((a)[2]), "r"((a)[3]), \
                   "r"((b)[0]), "r"((b)[1]))

#define CPASYNC16(dst, src) \
    asm volatile("cp.async.cg.shared.global [%0], [%1], 16;" :: "r"(dst), "l"(src))

// row stride in SMEM: 40 h16 = 80 bytes (odd multiple of 16B -> conflict-free ldmatrix)
#define RSTRIDE 80

// ---------------- pack (+ fused init; g_emb pre-seeded with b2) ----------------
__global__ void pack_split(const float* __restrict__ x, const float* __restrict__ b2) {
    int i = blockIdx.x * 1024 + threadIdx.x;      // exactly NROWS*DIN threads
    int r = i >> 9, c = i & 511;
    float v = x[(size_t)r * (DIN + 1) + 1 + c];
    h16 h, l; split2h(v, h, l);
    g_dataHi[i] = h; g_dataLo[i] = l;
    if (i < NROWS) g_labels[i] = (int)x[(size_t)i * (DIN + 1)];
    if (i < NROWS * EMBD) g_emb[i] = b2[i & (EMBD - 1)];    // bias seed for fused gemm2
    if (i < NCLS * 64) g_clsSum[i] = 0.f;
    if (i < NCLS) { g_clsSq[i] = 0.f; g_clsCnt[i] = 0; }
    if (i == 0) g_hinge = 0.f;
}

// ---------------- fused weight transpose (hi only) ----------------
__global__ void wtrans_all(const float* __restrict__ W1, const float* __restrict__ W2,
                           const float* __restrict__ W3, const float* __restrict__ W4) {
    __shared__ float t[32][33];
    int b = blockIdx.x;
    const float* W; h16* T; int K, N, bx, by;
    if (b < 512)      { W = W1; T = g_W1t; K = DIN;  N = HID;  int u = b;       bx = u % 32; by = u / 32; }
    else if (b < 576) { W = W2; T = g_W2t; K = HID;  N = EMBD; int u = b - 512; bx = u % 2;  by = u / 2;  }
    else if (b < 640) { W = W3; T = g_W3t; K = EMBD; N = HID;  int u = b - 576; bx = u % 32; by = u / 32; }
    else              { W = W4; T = g_W4t; K = HID;  N = DIN;  int u = b - 640; bx = u % 16; by = u / 16; }
    int tx = threadIdx.x, ty = threadIdx.y;
    int n0 = bx * 32, k0 = by * 32;
    t[ty][tx] = W[(size_t)(k0 + ty) * N + n0 + tx];
    __syncthreads();
    T[(size_t)(n0 + ty) * K + k0 + tx] = __float2half(t[tx][ty]);
}

// ---------------- fp16-split 2-pass mma.sync GEMM (R10-proven mainloop) ----------------
template<int BM, int BN, int WM, int WN, bool DOTANH, bool WF32, bool WBF>
__global__ void __launch_bounds__(32 * (BM / WM) * (BN / WN), 2)
gemm_mma(const h16* __restrict__ Ahi, const h16* __restrict__ Alo,
         const h16* __restrict__ Bhi,
         const float* __restrict__ bias,
         float* __restrict__ Cf, h16* __restrict__ CHi, h16* __restrict__ CLo,
         int N, int K)
{
    constexpr int WARPS_N = BN / WN;
    constexpr int NWARP   = (BM / WM) * WARPS_N;
    constexpr int THREADS = 32 * NWARP;
    constexpr int MI = WM / 16;
    constexpr int NJ = WN / 8;
    constexpr int ASZ   = BM * RSTRIDE;
    constexpr int BSZ   = BN * RSTRIDE;
    constexpr int STAGE = 2 * ASZ + BSZ;

    extern __shared__ char smem[];
    const uint32_t sb0 = s2u(smem);
    const int tid = threadIdx.x, lane = tid & 31, wid = tid >> 5;
    const int warp_m = wid / WARPS_N, warp_n = wid % WARPS_N;
    const int bx = blockIdx.x, by = blockIdx.y;

    const h16* aH = Ahi + (size_t)by * BM * K;
    const h16* aL = Alo + (size_t)by * BM * K;
    const h16* bH = Bhi + (size_t)bx * BN * K;

    const int KC = K >> 5;

    auto load_chunk = [&](int s, int kc) {
        uint32_t base = sb0 + s * STAGE;
        const int k0 = kc * 32;
        for (int idx = tid; idx < BM * 4; idx += THREADS) {
            int r = idx >> 2, p = idx & 3;
            uint32_t so = r * RSTRIDE + p * 16;
            CPASYNC16(base + so,        aH + (size_t)r * K + k0 + p * 8);
            CPASYNC16(base + ASZ + so,  aL + (size_t)r * K + k0 + p * 8);
        }
        for (int idx = tid; idx < BN * 4; idx += THREADS) {
            int r = idx >> 2, p = idx & 3;
            uint32_t so = r * RSTRIDE + p * 16;
            CPASYNC16(base + 2 * ASZ + so, bH + (size_t)r * K + k0 + p * 8);
        }
        asm volatile("cp.async.commit_group;");
    };

    float acc[MI][NJ][4];
#pragma unroll
    for (int i = 0; i < MI; i++)
#pragma unroll
        for (int j = 0; j < NJ; j++)
#pragma unroll
            for (int q = 0; q < 4; q++) acc[i][j][q] = 0.f;

    load_chunk(0, 0);

    for (int kc = 0; kc < KC; kc++) {
        if (kc + 1 < KC) {
            load_chunk((kc + 1) & 1, kc + 1);
            asm volatile("cp.async.wait_group 1;");
        } else {
            asm volatile("cp.async.wait_group 0;");
        }
        __syncthreads();

        uint32_t base = sb0 + (kc & 1) * STAGE;
        uint32_t aHb = base, aLb = base + ASZ, bHb = base + 2 * ASZ;

#pragma unroll
        for (int s16 = 0; s16 < 2; s16++) {
            uint32_t koff = s16 * 32 + ((lane >> 4) << 4);
            uint32_t ah[MI][4], al[MI][4], b[NJ][2];
#pragma unroll
            for (int mi = 0; mi < MI; mi++) {
                uint32_t ro = (uint32_t)(warp_m * WM + mi * 16 + (lane & 15)) * RSTRIDE + koff;
                LDSM4(ah[mi][0], ah[mi][1], ah[mi][2], ah[mi][3], aHb + ro);
            }
#pragma unroll
            for (int njp = 0; njp < NJ / 2; njp++) {
                uint32_t ro = (uint32_t)(warp_n * WN + njp * 16 + (lane & 15)) * RSTRIDE + koff;
                uint32_t r0, r1, r2, r3;
                LDSM4(r0, r1, r2, r3, bHb + ro);
                b[2 * njp][0] = r0; b[2 * njp + 1][0] = r1;
                b[2 * njp][1] = r2; b[2 * njp + 1][1] = r3;
            }
#pragma unroll
            for (int mi = 0; mi < MI; mi++) {
                uint32_t ro = (uint32_t)(warp_m * WM + mi * 16 + (lane & 15)) * RSTRIDE + koff;
                LDSM4(al[mi][0], al[mi][1], al[mi][2], al[mi][3], aLb + ro);
            }
#pragma unroll
            for (int mi = 0; mi < MI; mi++)
#pragma unroll
                for (int nj = 0; nj < NJ; nj++)
                    MMA16816(acc[mi][nj], ah[mi], b[nj]);
#pragma unroll
            for (int mi = 0; mi < MI; mi++)
#pragma unroll
                for (int nj = 0; nj < NJ; nj++)
                    MMA16816(acc[mi][nj], al[mi], b[nj]);
        }
        __syncthreads();
    }

#pragma unroll
    for (int mi = 0; mi < MI; mi++) {
#pragma unroll
        for (int nj = 0; nj < NJ; nj++) {
            int gr0 = by * BM + warp_m * WM + mi * 16 + (lane >> 2);
            int gc  = bx * BN + warp_n * WN + nj * 8 + 2 * (lane & 3);
            float bia0 = bias[gc], bia1 = bias[gc + 1];
#pragma unroll
            for (int half = 0; half < 2; half++) {
                int gr = gr0 + half * 8;
                float v0 = acc[mi][nj][2 * half]     + bia0;
                float v1 = acc[mi][nj][2 * half + 1] + bia1;
                if (DOTANH) { v0 = fast_tanh(v0); v1 = fast_tanh(v1); }
                if (WF32) {
                    *(float2*)&Cf[(size_t)gr * N + gc] = make_float2(v0, v1);
                }
                if (WBF) {
                    h16 h0, l0, h1, l1;
                    split2h(v0, h0, l0); split2h(v1, h1, l1);
                    *(__half2*)&CHi[(size_t)gr * N + gc] = __halves2half2(h0, h1);
                    *(__half2*)&CLo[(size_t)gr * N + gc] = __halves2half2(l0, l1);
                }
            }
        }
    }
}

// ---------------- GEMM1 fused with GEMM2: h1 never hits HBM ----------------
// h1tile = tanh(data@W1+b1) kept in smem; emb partial = h1tile @ W2slice, atomicAdd to g_emb.
// Fixed config: BM=128, BN=128, WM=64, WN=32, 256 threads, 8 warps.
// smem map: [0,61440) = 2 pipeline stages; after mainloop reused as h1 hi chunks [0,40960),
//           h1 lo chunks [40960,81920); W2 slice chunks at [81920,102400) (untouched by stages).
__global__ void __launch_bounds__(256, 2)
gemm1_fused(const h16* __restrict__ Ahi, const h16* __restrict__ Alo,
            const h16* __restrict__ Bhi, const h16* __restrict__ W2t,
            const float* __restrict__ bias, float* __restrict__ embOut)
{
    constexpr int K = DIN, N = HID;
    constexpr int ASZ   = 128 * RSTRIDE;          // 10240
    constexpr int BSZ   = 128 * RSTRIDE;
    constexpr int STAGE = 2 * ASZ + BSZ;          // 30720
    constexpr int MI = 4, NJ = 4;                 // 64x32 warp tiles, 2Mx4N warps
    constexpr int H1HI = 0, H1LO = 4 * ASZ, W2S = 8 * ASZ;   // chunk regions

    extern __shared__ char smem[];
    const uint32_t sb0 = s2u(smem);
    const int tid = threadIdx.x, lane = tid & 31, wid = tid >> 5;
    const int warp_m = wid / 4, warp_n = wid % 4;
    const int bx = blockIdx.x, by = blockIdx.y;

    const h16* aH = Ahi + (size_t)by * 128 * K;
    const h16* aL = Alo + (size_t)by * 128 * K;
    const h16* bH = Bhi + (size_t)bx * 128 * K;

    // W2 slice load: rows n=0..63 of W2t, cols bx*128..+128, into 4 chunk-format buffers
    {
        for (int v = 0; v < 4; v++) {
            int idx = tid + v * 256;              // 1024 16B vectors
            int c = idx >> 8, r = (idx >> 2) & 63, p = idx & 3;
            CPASYNC16(sb0 + W2S + c * (64 * RSTRIDE) + r * RSTRIDE + p * 16,
                      W2t + (size_t)r * HID + bx * 128 + c * 32 + p * 8);
        }
        // committed together with chunk 0 below
    }

    auto load_chunk = [&](int s, int kc) {
        uint32_t base = sb0 + s * STAGE;
        const int k0 = kc * 32;
        for (int idx = tid; idx < 128 * 4; idx += 256) {
            int r = idx >> 2, p = idx & 3;
            uint32_t so = r * RSTRIDE + p * 16;
            CPASYNC16(base + so,        aH + (size_t)r * K + k0 + p * 8);
            CPASYNC16(base + ASZ + so,  aL + (size_t)r * K + k0 + p * 8);
        }
        for (int idx = tid; idx < 128 * 4; idx += 256) {
            int r = idx >> 2, p = idx & 3;
            uint32_t so = r * RSTRIDE + p * 16;
            CPASYNC16(base + 2 * ASZ + so, bH + (size_t)r * K + k0 + p * 8);
        }
        asm volatile("cp.async.commit_group;");
    };

    float acc[MI][NJ][4];
#pragma unroll
    for (int i = 0; i < MI; i++)
#pragma unroll
        for (int j = 0; j < NJ; j++)
#pragma unroll
            for (int q = 0; q < 4; q++) acc[i][j][q] = 0.f;

    const int KC = K >> 5;                        // 16
    load_chunk(0, 0);

    for (int kc = 0; kc < KC; kc++) {
        if (kc + 1 < KC) {
            load_chunk((kc + 1) & 1, kc + 1);
            asm volatile("cp.async.wait_group 1;");
        } else {
            asm volatile("cp.async.wait_group 0;");
        }
        __syncthreads();

        uint32_t base = sb0 + (kc & 1) * STAGE;
        uint32_t aHb = base, aLb = base + ASZ, bHb = base + 2 * ASZ;

#pragma unroll
        for (int s16 = 0; s16 < 2; s16++) {
            uint32_t koff = s16 * 32 + ((lane >> 4) << 4);
            uint32_t ah[MI][4], al[MI][4], b[NJ][2];
#pragma unroll
            for (int mi = 0; mi < MI; mi++) {
                uint32_t ro = (uint32_t)(warp_m * 64 + mi * 16 + (lane & 15)) * RSTRIDE + koff;
                LDSM4(ah[mi][0], ah[mi][1], ah[mi][2], ah[mi][3], aHb + ro);
            }
#pragma unroll
            for (int njp = 0; njp < NJ / 2; njp++) {
                uint32_t ro = (uint32_t)(warp_n * 32 + njp * 16 + (lane & 15)) * RSTRIDE + koff;
                uint32_t r0, r1, r2, r3;
                LDSM4(r0, r1, r2, r3, bHb + ro);
                b[2 * njp][0] = r0; b[2 * njp + 1][0] = r1;
                b[2 * njp][1] = r2; b[2 * njp + 1][1] = r3;
            }
#pragma unroll
            for (int mi = 0; mi < MI; mi++) {
                uint32_t ro = (uint32_t)(warp_m * 64 + mi * 16 + (lane & 15)) * RSTRIDE + koff;
                LDSM4(al[mi][0], al[mi][1], al[mi][2], al[mi][3], aLb + ro);
            }
#pragma unroll
            for (int mi = 0; mi < MI; mi++)
#pragma unroll
                for (int nj = 0; nj < NJ; nj++)
                    MMA16816(acc[mi][nj], ah[mi], b[nj]);
#pragma unroll
            for (int mi = 0; mi < MI; mi++)
#pragma unroll
                for (int nj = 0; nj < NJ; nj++)
                    MMA16816(acc[mi][nj], al[mi], b[nj]);
        }
        __syncthreads();
    }

    // ---- epilogue 1: tanh + split -> smem h1 tile in chunk format ----
#pragma unroll
    for (int mi = 0; mi < MI; mi++) {
#pragma unroll
        for (int nj = 0; nj < NJ; nj++) {
            int lr0 = warp_m * 64 + mi * 16 + (lane >> 2);           // local row in tile
            int gc  = warp_n * 32 + nj * 8 + 2 * (lane & 3);         // local col (h1 col within 128)
            float bia0 = bias[bx * 128 + gc], bia1 = bias[bx * 128 + gc + 1];
            int chunk = gc >> 5, cb = gc & 31;
            uint32_t so = chunk * ASZ + (cb * 2);
#pragma unroll
            for (int half = 0; half < 2; half++) {
                int lr = lr0 + half * 8;
                float v0 = fast_tanh(acc[mi][nj][2 * half]     + bia0);
                float v1 = fast_tanh(acc[mi][nj][2 * half + 1] + bia1);
                h16 h0, l0, h1, l1;
                split2h(v0, h0, l0); split2h(v1, h1, l1);
                *(__half2*)(smem + H1HI + so + lr * RSTRIDE) = __halves2half2(h0, h1);
                *(__half2*)(smem + H1LO + so + lr * RSTRIDE) = __halves2half2(l0, l1);
            }
        }
    }
    __syncthreads();

    // ---- epilogue 2: mini-GEMM  emb_partial[128x64] = h1tile[128x128] @ W2slice^T ----
    const int warp_m2 = wid >> 1, warp_n2 = wid & 1;   // 4M x 2N, 32x32 warp tiles
    float acc2[2][4][4];
#pragma unroll
    for (int i = 0; i < 2; i++)
#pragma unroll
        for (int j = 0; j < 4; j++)
#pragma unroll
            for (int q = 0; q < 4; q++) acc2[i][j][q] = 0.f;

#pragma unroll
    for (int c = 0; c < 4; c++) {
        uint32_t aHb = sb0 + H1HI + c * ASZ;
        uint32_t aLb = sb0 + H1LO + c * ASZ;
        uint32_t bBb = sb0 + W2S + c * (64 * RSTRIDE);
#pragma unroll
        for (int s16 = 0; s16 < 2; s16++) {
            uint32_t koff = s16 * 32 + ((lane >> 4) << 4);
            uint32_t ah[2][4], al[2][4], b[4][2];
#pragma unroll
            for (int mi = 0; mi < 2; mi++) {
                uint32_t ro = (uint32_t)(warp_m2 * 32 + mi * 16 + (lane & 15)) * RSTRIDE + koff;
                LDSM4(ah[mi][0], ah[mi][1], ah[mi][2], ah[mi][3], aHb + ro);
                LDSM4(al[mi][0], al[mi][1], al[mi][2], al[mi][3], aLb + ro);
            }
#pragma unroll
            for (int njp = 0; njp < 2; njp++) {
                uint32_t ro = (uint32_t)(warp_n2 * 32 + njp * 16 + (lane & 15)) * RSTRIDE + koff;
                uint32_t r0, r1, r2, r3;
                LDSM4(r0, r1, r2, r3, bBb + ro);
                b[2 * njp][0] = r0; b[2 * njp + 1][0] = r1;
                b[2 * njp][1] = r2; b[2 * njp + 1][1] = r3;
            }
#pragma unroll
            for (int mi = 0; mi < 2; mi++)
#pragma unroll
                for (int nj = 0; nj < 4; nj++)
                    MMA16816(acc2[mi][nj], ah[mi], b[nj]);
#pragma unroll
            for (int mi = 0; mi < 2; mi++)
#pragma unroll
                for (int nj = 0; nj < 4; nj++)
                    MMA16816(acc2[mi][nj], al[mi], b[nj]);
        }
    }

    // accumulate partial emb into global (fp32 atomics; g_emb pre-seeded with b2)
#pragma unroll
    for (int mi = 0; mi < 2; mi++) {
#pragma unroll
        for (int nj = 0; nj < 4; nj++) {
            int gr0 = by * 128 + warp_m2 * 32 + mi * 16 + (lane >> 2);
            int gc  = warp_n2 * 32 + nj * 8 + 2 * (lane & 3);
#pragma unroll
            for (int half = 0; half < 2; half++) {
                int gr = gr0 + half * 8;
                atomicAdd(&embOut[(size_t)gr * EMBD + gc],     acc2[mi][nj][2 * half]);
                atomicAdd(&embOut[(size_t)gr * EMBD + gc + 1], acc2[mi][nj][2 * half + 1]);
            }
        }
    }
}

// ---------------- emb split pass: g_emb (complete) -> hi/lo fp16 ----------------
__global__ void emb_epi() {
    int i = blockIdx.x * 256 + threadIdx.x;       // NROWS*EMBD threads
    float v = g_emb[i];
    h16 h, l; split2h(v, h, l);
    g_embHi[i] = h; g_embLo[i] = l;
}

// ---------------- per-class sums, counts, member lists ----------------
__global__ void class_accum_kernel() {
    __shared__ float sSum[NCLS][64];
    __shared__ float sSq[NCLS];
    int tid = threadIdx.x;
    for (int i = tid; i < NCLS * 64; i += 256) ((float*)sSum)[i] = 0.f;
    if (tid < NCLS) sSq[tid] = 0.f;
    __syncthreads();

    int r = blockIdx.x * 256 + tid;
    int c = g_labels[r];
    const float* e = g_emb + (size_t)r * EMBD + 2;
    float sq = 0.f;
#pragma unroll
    for (int k = 0; k < NCONS; k++) {
        float v = e[k];
        sq = fmaf(v, v, sq);
        atomicAdd(&sSum[c][k], v);
    }
    atomicAdd(&sSq[c], sq);
    int pos = atomicAdd(&g_clsCnt[c], 1);
    if (pos < MAXC) g_members[c * MAXC + pos] = r;
    __syncthreads();

    for (int i = tid; i < NCLS * 64; i += 256) atomicAdd(&g_clsSum[i], ((float*)sSum)[i]);
    if (tid < NCLS) atomicAdd(&g_clsSq[tid], sSq[tid]);
}

// ---------------- same-class pairwise hinge (triangle x2, 64x64 tile, 4x4/thread) ----------------
__global__ void pair_kernel() {
    int c = blockIdx.z;
    int i0 = blockIdx.y * 64, j0 = blockIdx.x * 64;
    if (j0 > i0) return;
    int cnt = g_clsCnt[c]; if (cnt > MAXC) cnt = MAXC;
    if (i0 >= cnt || j0 >= cnt) return;
    float scale = (j0 < i0) ? 2.f : 1.f;

    __shared__ float va[64][63];
    __shared__ float vb[64][63];
    int tx = threadIdx.x, ty = threadIdx.y;    // 16 x 16
    int tid = ty * 16 + tx;

    {
        int r = tid >> 2, kk = tid & 3;
        int mi = g_members[c * MAXC + i0 + r];
        int mj = g_members[c * MAXC + j0 + r];
        bool iv = (i0 + r < cnt), jv = (j0 + r < cnt);
        const float* ei = g_emb + (size_t)mi * EMBD + 2;
        const float* ej = g_emb + (size_t)mj * EMBD + 2;
        for (int k = kk; k < NCONS; k += 4) {
            if (iv) va[r][k] = ei[k];
            if (jv) vb[r][k] = ej[k];
        }
    }
    __syncthreads();

    float d[4][4];
#pragma unroll
    for (int q = 0; q < 4; q++)
#pragma unroll
        for (int p = 0; p < 4; p++) d[q][p] = 0.f;
#pragma unroll
    for (int k = 0; k < NCONS; k++) {
        float a[4], bb[4];
#pragma unroll
        for (int q = 0; q < 4; q++) a[q] = va[ty + 16 * q][k];
#pragma unroll
        for (int p = 0; p < 4; p++) bb[p] = vb[tx + 16 * p][k];
#pragma unroll
        for (int q = 0; q < 4; q++)
#pragma unroll
            for (int p = 0; p < 4; p++) {
                float x = a[q] - bb[p];
                d[q][p] = fmaf(x, x, d[q][p]);
            }
    }
    const float inv = 1.0f / (float)NCONS;
    float h = 0.f;
#pragma unroll
    for (int q = 0; q < 4; q++) {
        bool iv = (i0 + ty + 16 * q < cnt);
#pragma unroll
        for (int p = 0; p < 4; p++) {
            bool jv = (j0 + tx + 16 * p < cnt);
            if (iv && jv) h += fmaxf(0.f, 0.01f - d[q][p] * inv);
        }
    }

#pragma unroll
    for (int o = 16; o > 0; o >>= 1) h += __shfl_down_sync(0xffffffffu, h, o);
    __shared__ float ws[8];
    int lane = tid & 31, wrp = tid >> 5;
    if (lane == 0) ws[wrp] = h;
    __syncthreads();
    if (tid < 8) {
        float v = ws[tid];
#pragma unroll
        for (int o = 4; o > 0; o >>= 1) v += __shfl_down_sync(0xffu, v, o);
        if (tid == 0) atomicAdd(&g_hinge, v * scale);
    }
}

// ---------------- finalize scalars (64 threads, fp64) ----------------
__global__ void finalize_kernel(float* __restrict__ out) {
    __shared__ double red[64];
    int k = threadIdx.x;
    double stk = 0.0;
    double same = 0.0, Stot = 0.0, n_same = 0.0;
    for (int c = 0; c < NCLS; c++) {
        double v = (k < NCONS) ? (double)g_clsSum[c * 64 + k] : 0.0;
        stk += v;
        red[k] = v * v;
        __syncthreads();
        for (int o = 32; o > 0; o >>= 1) {
            if (k < o) red[k] += red[k + o];
            __syncthreads();
        }
        if (k == 0) {
            double nc = (double)g_clsCnt[c], Sc = (double)g_clsSq[c];
            same  += 2.0 * nc * Sc - 2.0 * red[0];
            Stot  += Sc;
            n_same += nc * nc;
        }
        __syncthreads();
    }
    red[k] = stk * stk;
    __syncthreads();
    for (int o = 32; o > 0; o >>= 1) {
        if (k < o) red[k] += red[k + o];
        __syncthreads();
    }
    if (k == 0) {
        double stot2 = red[0];
        double total = (2.0 * (double)NROWS * Stot - 2.0 * stot2) / (double)NCONS;
        same /= (double)NCONS;
        double n_diff = (double)NROWS * (double)NROWS - n_same;
        out[(size_t)NROWS * DIN]     = (float)((total - same) / (n_diff + 1.0));
        out[(size_t)NROWS * DIN + 1] = (float)((double)g_hinge / (n_same + 1.0));
    }
}

// ---------------- launch ----------------
extern "C" void kernel_launch(void* const* d_in, const int* in_sizes, int n_in,
                              void* d_out, int out_size)
{
    (void)in_sizes; (void)n_in; (void)out_size;
    const float* x  = (const float*)d_in[0];
    const float* W1 = (const float*)d_in[1];
    const float* b1 = (const float*)d_in[2];
    const float* W2 = (const float*)d_in[3];
    const float* b2 = (const float*)d_in[4];
    const float* W3 = (const float*)d_in[5];
    const float* b3 = (const float*)d_in[6];
    const float* W4 = (const float*)d_in[7];
    const float* b4 = (const float*)d_in[8];
    float* out = (float*)d_out;

    void *pdH, *pdL, *peH, *peL, *p2H, *p2L, *pe;
    void *w1, *w2, *w3, *w4;
    cudaGetSymbolAddress(&pdH, g_dataHi); cudaGetSymbolAddress(&pdL, g_dataLo);
    cudaGetSymbolAddress(&peH, g_embHi);  cudaGetSymbolAddress(&peL, g_embLo);
    cudaGetSymbolAddress(&p2H, g_h2Hi);   cudaGetSymbolAddress(&p2L, g_h2Lo);
    cudaGetSymbolAddress(&pe,  g_emb);
    cudaGetSymbolAddress(&w1,  g_W1t);    cudaGetSymbolAddress(&w2,  g_W2t);
    cudaGetSymbolAddress(&w3,  g_W3t);    cudaGetSymbolAddress(&w4,  g_W4t);

    const int SMEM_BIG   = 2 * (2 * 128 + 128) * RSTRIDE;              // 61440
    const int SMEM_FUSED = (8 * 128 + 4 * 64) * RSTRIDE;               // 102400
    cudaFuncSetAttribute(gemm1_fused, cudaFuncAttributeMaxDynamicSharedMemorySize, SMEM_FUSED);
    cudaFuncSetAttribute(gemm_mma<128, 128, 64, 32, true,  false, true >, cudaFuncAttributeMaxDynamicSharedMemorySize, SMEM_BIG);
    cudaFuncSetAttribute(gemm_mma<128, 128, 64, 32, false, true,  false>, cudaFuncAttributeMaxDynamicSharedMemorySize, SMEM_BIG);

    pack_split<<<NROWS * DIN / 1024, 1024>>>(x, b2);         // launch 1 (init fused)
    wtrans_all<<<1152, dim3(32, 32)>>>(W1, W2, W3, W4);      // launch 2

    // h1 = tanh(data @ W1 + b1) fused with emb += h1 @ W2   (h1 stays in smem)
    gemm1_fused<<<dim3(HID / 128, NROWS / 128), 256, SMEM_FUSED>>>(
        (h16*)pdH, (h16*)pdL, (h16*)w1, (h16*)w2, b1, (float*)pe);
    // split complete emb -> hi/lo
    emb_epi<<<NROWS * EMBD / 256, 256>>>();
    // h2 = tanh(emb @ W3 + b3)    M=8192, N=1024, K=64
    gemm_mma<128, 128, 64, 32, true, false, true><<<dim3(HID / 128, NROWS / 128), 256, SMEM_BIG>>>(
        (h16*)peH, (h16*)peL, (h16*)w3, b3,
        nullptr, (h16*)p2H, (h16*)p2L, HID, EMBD);
    // decoded = h2 @ W4 + b4      M=8192, N=512, K=1024 -> fp32 out
    gemm_mma<128, 128, 64, 32, false, true, false><<<dim3(DIN / 128, NROWS / 128), 256, SMEM_BIG>>>(
        (h16*)p2H, (h16*)p2L, (h16*)w4, b4,
        out, nullptr, nullptr, DIN, HID);

    class_accum_kernel<<<NROWS / 256, 256>>>();
    pair_kernel<<<dim3(MAXC / 64, MAXC / 64, NCLS), dim3(16, 16)>>>();
    finalize_kernel<<<1, 64>>>(out);
}

// round 14
// speedup vs baseline: 1.0806x; 1.0100x over previous
#include <cuda_runtime.h>
#include <cuda_fp16.h>
#include <math.h>
#include <stdint.h>

#define NROWS 8192
#define DIN   512
#define HID   1024
#define EMBD  64
#define NCONS 62
#define NCLS  16
#define MAXC  1024
#define NSLAB 8

typedef __half h16;

// ---------------- scratch (device globals; no allocation) ----------------
__device__ h16   g_dataHi[NROWS * DIN], g_dataLo[NROWS * DIN];
__device__ h16   g_embHi[NROWS * EMBD], g_embLo[NROWS * EMBD];
__device__ h16   g_h2Hi[NROWS * HID],  g_h2Lo[NROWS * HID];
__device__ float g_emb[NROWS * EMBD];
__device__ float g_embPart[NSLAB * NROWS * EMBD];      // per-bx partial slabs (plain stores)
__device__ h16   g_W1t[HID * DIN];
__device__ h16   g_W2t[EMBD * HID];
__device__ h16   g_W3t[HID * EMBD];
__device__ h16   g_W4t[DIN * HID];
__device__ int   g_labels[NROWS];
__device__ float g_clsSum[NCLS * 64];
__device__ float g_clsSq[NCLS];
__device__ int   g_clsCnt[NCLS];
__device__ int   g_members[NCLS * MAXC];
__device__ float g_hinge;

// ---------------- small helpers ----------------
__device__ __forceinline__ void split2h(float v, h16& h, h16& l) {
    h = __float2half(v);
    l = __float2half(v - __half2float(h));
}

__device__ __forceinline__ float fast_tanh(float x) {
    float e = __expf(2.0f * x);
    return 1.0f - __fdividef(2.0f, e + 1.0f);
}

__device__ __forceinline__ uint32_t s2u(const void* p) {
    uint32_t r;
    asm("{ .reg .u64 t; cvta.to.shared.u64 t, %1; cvt.u32.u64 %0, t; }" : "=r"(r) : "l"(p));
    return r;
}

#define LDSM4(r0, r1, r2, r3, addr) \
    asm volatile("ldmatrix.sync.aligned.m8n8.x4.shared.b16 {%0,%1,%2,%3}, [%4];" \
                 : "=r"(r0), "=r"(r1), "=r"(r2), "=r"(r3) : "r"(addr))

#define MMA16816(c, a, b) \
    asm volatile("mma.sync.aligned.m16n8k16.row.col.f32.f16.f16.f32 " \
                 "{%0,%1,%2,%3}, {%4,%5,%6,%7}, {%8,%9}, {%0,%1,%2,%3};" \
                 : "+f"((c)[0]), "+f"((c)[1]), "+f"((c)[2]), "+f"((c)[3]) \
                 : "r"((a)[0]), "r"((a)[1]), "r"((a)[2]), "r"((a)[3]), \
                   "r"((b)[0]), "r"((b)[1]))

#define CPASYNC16(dst, src) \
    asm volatile("cp.async.cg.shared.global [%0], [%1], 16;" :: "r"(dst), "l"(src))

// row stride in SMEM: 40 h16 = 80 bytes (odd multiple of 16B -> conflict-free ldmatrix)
#define RSTRIDE 80

// ---------------- pack + weight transpose + init (single launch) ----------------
// blocks [0,4096): pack/split x; blocks [4096,5248): transpose W1..W4 (32x32 tiles)
__global__ void packw_all(const float* __restrict__ x,
                          const float* __restrict__ W1, const float* __restrict__ W2,
                          const float* __restrict__ W3, const float* __restrict__ W4) {
    if (blockIdx.x < 4096) {
        int i = blockIdx.x * 1024 + threadIdx.x;      // exactly NROWS*DIN threads
        int r = i >> 9, c = i & 511;
        float v = x[(size_t)r * (DIN + 1) + 1 + c];
        h16 h, l; split2h(v, h, l);
        g_dataHi[i] = h; g_dataLo[i] = l;
        if (i < NROWS) g_labels[i] = (int)x[(size_t)i * (DIN + 1)];
        if (i < NCLS * 64) g_clsSum[i] = 0.f;
        if (i < NCLS) { g_clsSq[i] = 0.f; g_clsCnt[i] = 0; }
        if (i == 0) g_hinge = 0.f;
        return;
    }
    __shared__ float t[32][33];
    int b = blockIdx.x - 4096;
    const float* W; h16* T; int K, N, bx, by;
    if (b < 512)      { W = W1; T = g_W1t; K = DIN;  N = HID;  int u = b;       bx = u % 32; by = u / 32; }
    else if (b < 576) { W = W2; T = g_W2t; K = HID;  N = EMBD; int u = b - 512; bx = u % 2;  by = u / 2;  }
    else if (b < 640) { W = W3; T = g_W3t; K = EMBD; N = HID;  int u = b - 576; bx = u % 32; by = u / 32; }
    else              { W = W4; T = g_W4t; K = HID;  N = DIN;  int u = b - 640; bx = u % 16; by = u / 16; }
    int tx = threadIdx.x & 31, ty = threadIdx.x >> 5;
    int n0 = bx * 32, k0 = by * 32;
    t[ty][tx] = W[(size_t)(k0 + ty) * N + n0 + tx];
    __syncthreads();
    T[(size_t)(n0 + ty) * K + k0 + tx] = __float2half(t[tx][ty]);
}

// ---------------- fp16-split 2-pass mma.sync GEMM (R10-proven mainloop) ----------------
template<int BM, int BN, int WM, int WN, bool DOTANH, bool WF32, bool WBF>
__global__ void __launch_bounds__(32 * (BM / WM) * (BN / WN), 2)
gemm_mma(const h16* __restrict__ Ahi, const h16* __restrict__ Alo,
         const h16* __restrict__ Bhi,
         const float* __restrict__ bias,
         float* __restrict__ Cf, h16* __restrict__ CHi, h16* __restrict__ CLo,
         int N, int K)
{
    constexpr int WARPS_N = BN / WN;
    constexpr int NWARP   = (BM / WM) * WARPS_N;
    constexpr int THREADS = 32 * NWARP;
    constexpr int MI = WM / 16;
    constexpr int NJ = WN / 8;
    constexpr int ASZ   = BM * RSTRIDE;
    constexpr int BSZ   = BN * RSTRIDE;
    constexpr int STAGE = 2 * ASZ + BSZ;

    extern __shared__ char smem[];
    const uint32_t sb0 = s2u(smem);
    const int tid = threadIdx.x, lane = tid & 31, wid = tid >> 5;
    const int warp_m = wid / WARPS_N, warp_n = wid % WARPS_N;
    const int bx = blockIdx.x, by = blockIdx.y;

    const h16* aH = Ahi + (size_t)by * BM * K;
    const h16* aL = Alo + (size_t)by * BM * K;
    const h16* bH = Bhi + (size_t)bx * BN * K;

    const int KC = K >> 5;

    auto load_chunk = [&](int s, int kc) {
        uint32_t base = sb0 + s * STAGE;
        const int k0 = kc * 32;
        for (int idx = tid; idx < BM * 4; idx += THREADS) {
            int r = idx >> 2, p = idx & 3;
            uint32_t so = r * RSTRIDE + p * 16;
            CPASYNC16(base + so,        aH + (size_t)r * K + k0 + p * 8);
            CPASYNC16(base + ASZ + so,  aL + (size_t)r * K + k0 + p * 8);
        }
        for (int idx = tid; idx < BN * 4; idx += THREADS) {
            int r = idx >> 2, p = idx & 3;
            uint32_t so = r * RSTRIDE + p * 16;
            CPASYNC16(base + 2 * ASZ + so, bH + (size_t)r * K + k0 + p * 8);
        }
        asm volatile("cp.async.commit_group;");
    };

    float acc[MI][NJ][4];
#pragma unroll
    for (int i = 0; i < MI; i++)
#pragma unroll
        for (int j = 0; j < NJ; j++)
#pragma unroll
            for (int q = 0; q < 4; q++) acc[i][j][q] = 0.f;

    load_chunk(0, 0);

    for (int kc = 0; kc < KC; kc++) {
        if (kc + 1 < KC) {
            load_chunk((kc + 1) & 1, kc + 1);
            asm volatile("cp.async.wait_group 1;");
        } else {
            asm volatile("cp.async.wait_group 0;");
        }
        __syncthreads();

        uint32_t base = sb0 + (kc & 1) * STAGE;
        uint32_t aHb = base, aLb = base + ASZ, bHb = base + 2 * ASZ;

#pragma unroll
        for (int s16 = 0; s16 < 2; s16++) {
            uint32_t koff = s16 * 32 + ((lane >> 4) << 4);
            uint32_t ah[MI][4], al[MI][4], b[NJ][2];
#pragma unroll
            for (int mi = 0; mi < MI; mi++) {
                uint32_t ro = (uint32_t)(warp_m * WM + mi * 16 + (lane & 15)) * RSTRIDE + koff;
                LDSM4(ah[mi][0], ah[mi][1], ah[mi][2], ah[mi][3], aHb + ro);
            }
#pragma unroll
            for (int njp = 0; njp < NJ / 2; njp++) {
                uint32_t ro = (uint32_t)(warp_n * WN + njp * 16 + (lane & 15)) * RSTRIDE + koff;
                uint32_t r0, r1, r2, r3;
                LDSM4(r0, r1, r2, r3, bHb + ro);
                b[2 * njp][0] = r0; b[2 * njp + 1][0] = r1;
                b[2 * njp][1] = r2; b[2 * njp + 1][1] = r3;
            }
#pragma unroll
            for (int mi = 0; mi < MI; mi++) {
                uint32_t ro = (uint32_t)(warp_m * WM + mi * 16 + (lane & 15)) * RSTRIDE + koff;
                LDSM4(al[mi][0], al[mi][1], al[mi][2], al[mi][3], aLb + ro);
            }
#pragma unroll
            for (int mi = 0; mi < MI; mi++)
#pragma unroll
                for (int nj = 0; nj < NJ; nj++)
                    MMA16816(acc[mi][nj], ah[mi], b[nj]);
#pragma unroll
            for (int mi = 0; mi < MI; mi++)
#pragma unroll
                for (int nj = 0; nj < NJ; nj++)
                    MMA16816(acc[mi][nj], al[mi], b[nj]);
        }
        __syncthreads();
    }

#pragma unroll
    for (int mi = 0; mi < MI; mi++) {
#pragma unroll
        for (int nj = 0; nj < NJ; nj++) {
            int gr0 = by * BM + warp_m * WM + mi * 16 + (lane >> 2);
            int gc  = bx * BN + warp_n * WN + nj * 8 + 2 * (lane & 3);
            float bia0 = bias[gc], bia1 = bias[gc + 1];
#pragma unroll
            for (int half = 0; half < 2; half++) {
                int gr = gr0 + half * 8;
                float v0 = acc[mi][nj][2 * half]     + bia0;
                float v1 = acc[mi][nj][2 * half + 1] + bia1;
                if (DOTANH) { v0 = fast_tanh(v0); v1 = fast_tanh(v1); }
                if (WF32) {
                    *(float2*)&Cf[(size_t)gr * N + gc] = make_float2(v0, v1);
                }
                if (WBF) {
                    h16 h0, l0, h1, l1;
                    split2h(v0, h0, l0); split2h(v1, h1, l1);
                    *(__half2*)&CHi[(size_t)gr * N + gc] = __halves2half2(h0, h1);
                    *(__half2*)&CLo[(size_t)gr * N + gc] = __halves2half2(l0, l1);
                }
            }
        }
    }
}

// ---------------- GEMM1 fused with GEMM2: h1 never hits HBM ----------------
// h1tile = tanh(data@W1+b1) kept in smem; emb partial = h1tile @ W2slice -> slab bx (plain stores).
__global__ void __launch_bounds__(256, 2)
gemm1_fused(const h16* __restrict__ Ahi, const h16* __restrict__ Alo,
            const h16* __restrict__ Bhi, const h16* __restrict__ W2t,
            const float* __restrict__ bias, float* __restrict__ embPart)
{
    constexpr int K = DIN, N = HID;
    constexpr int ASZ   = 128 * RSTRIDE;          // 10240
    constexpr int BSZ   = 128 * RSTRIDE;
    constexpr int STAGE = 2 * ASZ + BSZ;          // 30720
    constexpr int MI = 4, NJ = 4;
    constexpr int H1HI = 0, H1LO = 4 * ASZ, W2S = 8 * ASZ;

    extern __shared__ char smem[];
    const uint32_t sb0 = s2u(smem);
    const int tid = threadIdx.x, lane = tid & 31, wid = tid >> 5;
    const int warp_m = wid / 4, warp_n = wid % 4;
    const int bx = blockIdx.x, by = blockIdx.y;

    const h16* aH = Ahi + (size_t)by * 128 * K;
    const h16* aL = Alo + (size_t)by * 128 * K;
    const h16* bH = Bhi + (size_t)bx * 128 * K;

    // W2 slice load into chunk-format buffers (committed with chunk 0)
    {
        for (int v = 0; v < 4; v++) {
            int idx = tid + v * 256;
            int c = idx >> 8, r = (idx >> 2) & 63, p = idx & 3;
            CPASYNC16(sb0 + W2S + c * (64 * RSTRIDE) + r * RSTRIDE + p * 16,
                      W2t + (size_t)r * HID + bx * 128 + c * 32 + p * 8);
        }
    }

    auto load_chunk = [&](int s, int kc) {
        uint32_t base = sb0 + s * STAGE;
        const int k0 = kc * 32;
        for (int idx = tid; idx < 128 * 4; idx += 256) {
            int r = idx >> 2, p = idx & 3;
            uint32_t so = r * RSTRIDE + p * 16;
            CPASYNC16(base + so,        aH + (size_t)r * K + k0 + p * 8);
            CPASYNC16(base + ASZ + so,  aL + (size_t)r * K + k0 + p * 8);
        }
        for (int idx = tid; idx < 128 * 4; idx += 256) {
            int r = idx >> 2, p = idx & 3;
            uint32_t so = r * RSTRIDE + p * 16;
            CPASYNC16(base + 2 * ASZ + so, bH + (size_t)r * K + k0 + p * 8);
        }
        asm volatile("cp.async.commit_group;");
    };

    float acc[MI][NJ][4];
#pragma unroll
    for (int i = 0; i < MI; i++)
#pragma unroll
        for (int j = 0; j < NJ; j++)
#pragma unroll
            for (int q = 0; q < 4; q++) acc[i][j][q] = 0.f;

    const int KC = K >> 5;
    load_chunk(0, 0);

    for (int kc = 0; kc < KC; kc++) {
        if (kc + 1 < KC) {
            load_chunk((kc + 1) & 1, kc + 1);
            asm volatile("cp.async.wait_group 1;");
        } else {
            asm volatile("cp.async.wait_group 0;");
        }
        __syncthreads();

        uint32_t base = sb0 + (kc & 1) * STAGE;
        uint32_t aHb = base, aLb = base + ASZ, bHb = base + 2 * ASZ;

#pragma unroll
        for (int s16 = 0; s16 < 2; s16++) {
            uint32_t koff = s16 * 32 + ((lane >> 4) << 4);
            uint32_t ah[MI][4], al[MI][4], b[NJ][2];
#pragma unroll
            for (int mi = 0; mi < MI; mi++) {
                uint32_t ro = (uint32_t)(warp_m * 64 + mi * 16 + (lane & 15)) * RSTRIDE + koff;
                LDSM4(ah[mi][0], ah[mi][1], ah[mi][2], ah[mi][3], aHb + ro);
            }
#pragma unroll
            for (int njp = 0; njp < NJ / 2; njp++) {
                uint32_t ro = (uint32_t)(warp_n * 32 + njp * 16 + (lane & 15)) * RSTRIDE + koff;
                uint32_t r0, r1, r2, r3;
                LDSM4(r0, r1, r2, r3, bHb + ro);
                b[2 * njp][0] = r0; b[2 * njp + 1][0] = r1;
                b[2 * njp][1] = r2; b[2 * njp + 1][1] = r3;
            }
#pragma unroll
            for (int mi = 0; mi < MI; mi++) {
                uint32_t ro = (uint32_t)(warp_m * 64 + mi * 16 + (lane & 15)) * RSTRIDE + koff;
                LDSM4(al[mi][0], al[mi][1], al[mi][2], al[mi][3], aLb + ro);
            }
#pragma unroll
            for (int mi = 0; mi < MI; mi++)
#pragma unroll
                for (int nj = 0; nj < NJ; nj++)
                    MMA16816(acc[mi][nj], ah[mi], b[nj]);
#pragma unroll
            for (int mi = 0; mi < MI; mi++)
#pragma unroll
                for (int nj = 0; nj < NJ; nj++)
                    MMA16816(acc[mi][nj], al[mi], b[nj]);
        }
        __syncthreads();
    }

    // ---- epilogue 1: tanh + split -> smem h1 tile in chunk format ----
#pragma unroll
    for (int mi = 0; mi < MI; mi++) {
#pragma unroll
        for (int nj = 0; nj < NJ; nj++) {
            int lr0 = warp_m * 64 + mi * 16 + (lane >> 2);
            int gc  = warp_n * 32 + nj * 8 + 2 * (lane & 3);
            float bia0 = bias[bx * 128 + gc], bia1 = bias[bx * 128 + gc + 1];
            int chunk = gc >> 5, cb = gc & 31;
            uint32_t so = chunk * ASZ + (cb * 2);
#pragma unroll
            for (int half = 0; half < 2; half++) {
                int lr = lr0 + half * 8;
                float v0 = fast_tanh(acc[mi][nj][2 * half]     + bia0);
                float v1 = fast_tanh(acc[mi][nj][2 * half + 1] + bia1);
                h16 h0, l0, h1, l1;
                split2h(v0, h0, l0); split2h(v1, h1, l1);
                *(__half2*)(smem + H1HI + so + lr * RSTRIDE) = __halves2half2(h0, h1);
                *(__half2*)(smem + H1LO + so + lr * RSTRIDE) = __halves2half2(l0, l1);
            }
        }
    }
    __syncthreads();

    // ---- epilogue 2: mini-GEMM  emb_partial[128x64] = h1tile @ W2slice^T -> slab bx ----
    const int warp_m2 = wid >> 1, warp_n2 = wid & 1;   // 4M x 2N, 32x32 warp tiles
    float acc2[2][4][4];
#pragma unroll
    for (int i = 0; i < 2; i++)
#pragma unroll
        for (int j = 0; j < 4; j++)
#pragma unroll
            for (int q = 0; q < 4; q++) acc2[i][j][q] = 0.f;

#pragma unroll
    for (int c = 0; c < 4; c++) {
        uint32_t aHb = sb0 + H1HI + c * ASZ;
        uint32_t aLb = sb0 + H1LO + c * ASZ;
        uint32_t bBb = sb0 + W2S + c * (64 * RSTRIDE);
#pragma unroll
        for (int s16 = 0; s16 < 2; s16++) {
            uint32_t koff = s16 * 32 + ((lane >> 4) << 4);
            uint32_t ah[2][4], al[2][4], b[4][2];
#pragma unroll
            for (int mi = 0; mi < 2; mi++) {
                uint32_t ro = (uint32_t)(warp_m2 * 32 + mi * 16 + (lane & 15)) * RSTRIDE + koff;
                LDSM4(ah[mi][0], ah[mi][1], ah[mi][2], ah[mi][3], aHb + ro);
                LDSM4(al[mi][0], al[mi][1], al[mi][2], al[mi][3], aLb + ro);
            }
#pragma unroll
            for (int njp = 0; njp < 2; njp++) {
                uint32_t ro = (uint32_t)(warp_n2 * 32 + njp * 16 + (lane & 15)) * RSTRIDE + koff;
                uint32_t r0, r1, r2, r3;
                LDSM4(r0, r1, r2, r3, bBb + ro);
                b[2 * njp][0] = r0; b[2 * njp + 1][0] = r1;
                b[2 * njp][1] = r2; b[2 * njp + 1][1] = r3;
            }
#pragma unroll
            for (int mi = 0; mi < 2; mi++)
#pragma unroll
                for (int nj = 0; nj < 4; nj++)
                    MMA16816(acc2[mi][nj], ah[mi], b[nj]);
#pragma unroll
            for (int mi = 0; mi < 2; mi++)
#pragma unroll
                for (int nj = 0; nj < 4; nj++)
                    MMA16816(acc2[mi][nj], al[mi], b[nj]);
        }
    }

    // plain vectorized stores to this CTA's slab (no atomics)
    float* slab = embPart + (size_t)bx * (NROWS * EMBD);
#pragma unroll
    for (int mi = 0; mi < 2; mi++) {
#pragma unroll
        for (int nj = 0; nj < 4; nj++) {
            int gr0 = by * 128 + warp_m2 * 32 + mi * 16 + (lane >> 2);
            int gc  = warp_n2 * 32 + nj * 8 + 2 * (lane & 3);
#pragma unroll
            for (int half = 0; half < 2; half++) {
                int gr = gr0 + half * 8;
                *(float2*)&slab[(size_t)gr * EMBD + gc] =
                    make_float2(acc2[mi][nj][2 * half], acc2[mi][nj][2 * half + 1]);
            }
        }
    }
}

// ---------------- emb reduce (8 slabs + bias) + split -> g_emb, hi/lo ----------------
__global__ void emb_epi(const float* __restrict__ b2) {
    int i = blockIdx.x * 256 + threadIdx.x;       // NROWS*EMBD threads
    float v = b2[i & (EMBD - 1)];
    const int S = NROWS * EMBD;
#pragma unroll
    for (int s = 0; s < NSLAB; s++) v += g_embPart[(size_t)s * S + i];
    g_emb[i] = v;
    h16 h, l; split2h(v, h, l);
    g_embHi[i] = h; g_embLo[i] = l;
}

// ---------------- per-class sums, counts, member lists ----------------
__global__ void class_accum_kernel() {
    __shared__ float sSum[NCLS][64];
    __shared__ float sSq[NCLS];
    int tid = threadIdx.x;
    for (int i = tid; i < NCLS * 64; i += 256) ((float*)sSum)[i] = 0.f;
    if (tid < NCLS) sSq[tid] = 0.f;
    __syncthreads();

    int r = blockIdx.x * 256 + tid;
    int c = g_labels[r];
    const float* e = g_emb + (size_t)r * EMBD + 2;
    float sq = 0.f;
#pragma unroll
    for (int k = 0; k < NCONS; k++) {
        float v = e[k];
        sq = fmaf(v, v, sq);
        atomicAdd(&sSum[c][k], v);
    }
    atomicAdd(&sSq[c], sq);
    int pos = atomicAdd(&g_clsCnt[c], 1);
    if (pos < MAXC) g_members[c * MAXC + pos] = r;
    __syncthreads();

    for (int i = tid; i < NCLS * 64; i += 256) atomicAdd(&g_clsSum[i], ((float*)sSum)[i]);
    if (tid < NCLS) atomicAdd(&g_clsSq[tid], sSq[tid]);
}

// ---------------- same-class pairwise hinge (triangle x2, 64x64 tile, 4x4/thread) ----------------
__global__ void pair_kernel() {
    int c = blockIdx.z;
    int i0 = blockIdx.y * 64, j0 = blockIdx.x * 64;
    if (j0 > i0) return;
    int cnt = g_clsCnt[c]; if (cnt > MAXC) cnt = MAXC;
    if (i0 >= cnt || j0 >= cnt) return;
    float scale = (j0 < i0) ? 2.f : 1.f;

    __shared__ float va[64][63];
    __shared__ float vb[64][63];
    int tx = threadIdx.x, ty = threadIdx.y;    // 16 x 16
    int tid = ty * 16 + tx;

    {
        int r = tid >> 2, kk = tid & 3;
        int mi = g_members[c * MAXC + i0 + r];
        int mj = g_members[c * MAXC + j0 + r];
        bool iv = (i0 + r < cnt), jv = (j0 + r < cnt);
        const float* ei = g_emb + (size_t)mi * EMBD + 2;
        const float* ej = g_emb + (size_t)mj * EMBD + 2;
        for (int k = kk; k < NCONS; k += 4) {
            if (iv) va[r][k] = ei[k];
            if (jv) vb[r][k] = ej[k];
        }
    }
    __syncthreads();

    float d[4][4];
#pragma unroll
    for (int q = 0; q < 4; q++)
#pragma unroll
        for (int p = 0; p < 4; p++) d[q][p] = 0.f;
#pragma unroll
    for (int k = 0; k < NCONS; k++) {
        float a[4], bb[4];
#pragma unroll
        for (int q = 0; q < 4; q++) a[q] = va[ty + 16 * q][k];
#pragma unroll
        for (int p = 0; p < 4; p++) bb[p] = vb[tx + 16 * p][k];
#pragma unroll
        for (int q = 0; q < 4; q++)
#pragma unroll
            for (int p = 0; p < 4; p++) {
                float x = a[q] - bb[p];
                d[q][p] = fmaf(x, x, d[q][p]);
            }
    }
    const float inv = 1.0f / (float)NCONS;
    float h = 0.f;
#pragma unroll
    for (int q = 0; q < 4; q++) {
        bool iv = (i0 + ty + 16 * q < cnt);
#pragma unroll
        for (int p = 0; p < 4; p++) {
            bool jv = (j0 + tx + 16 * p < cnt);
            if (iv && jv) h += fmaxf(0.f, 0.01f - d[q][p] * inv);
        }
    }

#pragma unroll
    for (int o = 16; o > 0; o >>= 1) h += __shfl_down_sync(0xffffffffu, h, o);
    __shared__ float ws[8];
    int lane = tid & 31, wrp = tid >> 5;
    if (lane == 0) ws[wrp] = h;
    __syncthreads();
    if (tid < 8) {
        float v = ws[tid];
#pragma unroll
        for (int o = 4; o > 0; o >>= 1) v += __shfl_down_sync(0xffu, v, o);
        if (tid == 0) atomicAdd(&g_hinge, v * scale);
    }
}

// ---------------- finalize scalars (64 threads, fp64) ----------------
__global__ void finalize_kernel(float* __restrict__ out) {
    __shared__ double red[64];
    int k = threadIdx.x;
    double stk = 0.0;
    double same = 0.0, Stot = 0.0, n_same = 0.0;
    for (int c = 0; c < NCLS; c++) {
        double v = (k < NCONS) ? (double)g_clsSum[c * 64 + k] : 0.0;
        stk += v;
        red[k] = v * v;
        __syncthreads();
        for (int o = 32; o > 0; o >>= 1) {
            if (k < o) red[k] += red[k + o];
            __syncthreads();
        }
        if (k == 0) {
            double nc = (double)g_clsCnt[c], Sc = (double)g_clsSq[c];
            same  += 2.0 * nc * Sc - 2.0 * red[0];
            Stot  += Sc;
            n_same += nc * nc;
        }
        __syncthreads();
    }
    red[k] = stk * stk;
    __syncthreads();
    for (int o = 32; o > 0; o >>= 1) {
        if (k < o) red[k] += red[k + o];
        __syncthreads();
    }
    if (k == 0) {
        double stot2 = red[0];
        double total = (2.0 * (double)NROWS * Stot - 2.0 * stot2) / (double)NCONS;
        same /= (double)NCONS;
        double n_diff = (double)NROWS * (double)NROWS - n_same;
        out[(size_t)NROWS * DIN]     = (float)((total - same) / (n_diff + 1.0));
        out[(size_t)NROWS * DIN + 1] = (float)((double)g_hinge / (n_same + 1.0));
    }
}

// ---------------- launch ----------------
extern "C" void kernel_launch(void* const* d_in, const int* in_sizes, int n_in,
                              void* d_out, int out_size)
{
    (void)in_sizes; (void)n_in; (void)out_size;
    const float* x  = (const float*)d_in[0];
    const float* W1 = (const float*)d_in[1];
    const float* b1 = (const float*)d_in[2];
    const float* W2 = (const float*)d_in[3];
    const float* b2 = (const float*)d_in[4];
    const float* W3 = (const float*)d_in[5];
    const float* b3 = (const float*)d_in[6];
    const float* W4 = (const float*)d_in[7];
    const float* b4 = (const float*)d_in[8];
    float* out = (float*)d_out;

    void *pdH, *pdL, *peH, *peL, *p2H, *p2L, *pep;
    void *w1, *w2, *w3, *w4;
    cudaGetSymbolAddress(&pdH, g_dataHi); cudaGetSymbolAddress(&pdL, g_dataLo);
    cudaGetSymbolAddress(&peH, g_embHi);  cudaGetSymbolAddress(&peL, g_embLo);
    cudaGetSymbolAddress(&p2H, g_h2Hi);   cudaGetSymbolAddress(&p2L, g_h2Lo);
    cudaGetSymbolAddress(&pep, g_embPart);
    cudaGetSymbolAddress(&w1,  g_W1t);    cudaGetSymbolAddress(&w2,  g_W2t);
    cudaGetSymbolAddress(&w3,  g_W3t);    cudaGetSymbolAddress(&w4,  g_W4t);

    const int SMEM_BIG   = 2 * (2 * 128 + 128) * RSTRIDE;              // 61440
    const int SMEM_FUSED = (8 * 128 + 4 * 64) * RSTRIDE;               // 102400
    cudaFuncSetAttribute(gemm1_fused, cudaFuncAttributeMaxDynamicSharedMemorySize, SMEM_FUSED);
    cudaFuncSetAttribute(gemm_mma<128, 128, 64, 32, true,  false, true >, cudaFuncAttributeMaxDynamicSharedMemorySize, SMEM_BIG);
    cudaFuncSetAttribute(gemm_mma<128, 128, 64, 32, false, true,  false>, cudaFuncAttributeMaxDynamicSharedMemorySize, SMEM_BIG);

    packw_all<<<5248, 1024>>>(x, W1, W2, W3, W4);            // launch 1 (pack + wtrans + init)

    // h1 = tanh(data @ W1 + b1) fused with emb slab = h1 @ W2   (h1 stays in smem)
    gemm1_fused<<<dim3(HID / 128, NROWS / 128), 256, SMEM_FUSED>>>(
        (h16*)pdH, (h16*)pdL, (h16*)w1, (h16*)w2, b1, (float*)pep);
    // reduce slabs + bias -> g_emb, hi/lo
    emb_epi<<<NROWS * EMBD / 256, 256>>>(b2);
    // h2 = tanh(emb @ W3 + b3)    M=8192, N=1024, K=64
    gemm_mma<128, 128, 64, 32, true, false, true><<<dim3(HID / 128, NROWS / 128), 256, SMEM_BIG>>>(
        (h16*)peH, (h16*)peL, (h16*)w3, b3,
        nullptr, (h16*)p2H, (h16*)p2L, HID, EMBD);
    // decoded = h2 @ W4 + b4      M=8192, N=512, K=1024 -> fp32 out
    gemm_mma<128, 128, 64, 32, false, true, false><<<dim3(DIN / 128, NROWS / 128), 256, SMEM_BIG>>>(
        (h16*)p2H, (h16*)p2L, (h16*)w4, b4,
        out, nullptr, nullptr, DIN, HID);

    class_accum_kernel<<<NROWS / 256, 256>>>();
    pair_kernel<<<dim3(MAXC / 64, MAXC / 64, NCLS), dim3(16, 16)>>>();
    finalize_kernel<<<1, 64>>>(out);
}